// round 1
// baseline (speedup 1.0000x reference)
#include <cuda_runtime.h>
#include <math.h>

#define BB   64
#define VV   30
#define DD   640
#define DINN 1280
#define DSS  16
#define DTRR 40
#define DCC  4
#define NLL  4
#define MM   (BB*VV)          // 1920
#define DBLW (DTRR + 2*DSS)   // 72

// ---------------- scratch (device globals; no runtime allocation) ----------
__device__ float g_h[MM*DD];
__device__ float g_xn[MM*DD];
__device__ float g_z[MM*2*DINN];     // in_proj output: [:,0:DIN]=u, [:,DIN:2DIN]=res
__device__ float g_uc[MM*DINN];      // conv+silu output
__device__ float g_dbl[MM*DBLW];     // x_proj output (delta_raw | B | C)
__device__ float g_delta[MM*DINN];   // dt_proj output, then softplus in-place
__device__ float g_y[MM*DINN];       // scan output
__device__ float g_y2[MM*DINN];      // gated

// ---------------- permute (fwd: rev=0, reverse: rev=1) ---------------------
__global__ void k_permute(const float* __restrict__ in, const int* __restrict__ vs,
                          float* __restrict__ out, int rev)
{
    int idx = blockIdx.x * blockDim.x + threadIdx.x;
    if (idx >= MM*DD) return;
    int d = idx % DD;
    int m = idx / DD;
    int t = m % VV, b = m / VV;
    int v = vs[b];
    int src = rev ? ((t + v) % VV) : ((t + VV - v) % VV);
    out[idx] = in[(b*VV + src)*DD + d];
}

// ---------------- RMSNorm over D=640, one block per row --------------------
__global__ void k_rmsnorm(const float* __restrict__ in, const float* __restrict__ w,
                          float* __restrict__ out)
{
    int m = blockIdx.x;
    const float* row = in + m*DD;
    float ss = 0.f;
    for (int i = threadIdx.x; i < DD; i += blockDim.x) { float v = row[i]; ss += v*v; }
    __shared__ float red[32];
    for (int o = 16; o; o >>= 1) ss += __shfl_xor_sync(0xffffffffu, ss, o);
    if ((threadIdx.x & 31) == 0) red[threadIdx.x >> 5] = ss;
    __syncthreads();
    if (threadIdx.x < 32) {
        float v = (threadIdx.x < (blockDim.x >> 5)) ? red[threadIdx.x] : 0.f;
        for (int o = 16; o; o >>= 1) v += __shfl_xor_sync(0xffffffffu, v, o);
        red[threadIdx.x] = v;
    }
    __syncthreads();
    float scale = rsqrtf(red[0] * (1.f/DD) + 1e-5f);
    for (int i = threadIdx.x; i < DD; i += blockDim.x)
        out[m*DD + i] = row[i] * scale * w[i];
}

// ---------------- generic SGEMM: C[M,N] = A[M,K] * W[N,K]^T (+C) -----------
// 64x64 block tile, 16 k-tile, 256 threads, 4x4 register tile per thread.
__global__ void k_sgemm(const float* __restrict__ A, int lda,
                        const float* __restrict__ W,
                        float* __restrict__ C, int ldc,
                        int M, int N, int K, int accumulate)
{
    __shared__ float As[16][64];
    __shared__ float Ws[16][64];
    int tid = threadIdx.x;
    int m0 = blockIdx.y * 64;
    int n0 = blockIdx.x * 64;
    int tr = tid >> 4;        // 0..15
    int tc = tid & 15;        // 0..15
    int lr = tid >> 2;        // 0..63 (load row)
    int lk = (tid & 3) * 4;   // 0,4,8,12

    float acc[4][4];
#pragma unroll
    for (int i = 0; i < 4; i++)
#pragma unroll
        for (int j = 0; j < 4; j++) acc[i][j] = 0.f;

    for (int k0 = 0; k0 < K; k0 += 16) {
        int am = m0 + lr;
        int wn = n0 + lr;
#pragma unroll
        for (int j = 0; j < 4; j++) {
            int k = k0 + lk + j;
            As[lk + j][lr] = (k < K && am < M) ? A[(long)am * lda + k] : 0.f;
            Ws[lk + j][lr] = (k < K && wn < N) ? W[(long)wn * K   + k] : 0.f;
        }
        __syncthreads();
#pragma unroll
        for (int kk = 0; kk < 16; kk++) {
            float av[4], wv[4];
#pragma unroll
            for (int i = 0; i < 4; i++) av[i] = As[kk][tr*4 + i];
#pragma unroll
            for (int j = 0; j < 4; j++) wv[j] = Ws[kk][tc*4 + j];
#pragma unroll
            for (int i = 0; i < 4; i++)
#pragma unroll
                for (int j = 0; j < 4; j++) acc[i][j] += av[i] * wv[j];
        }
        __syncthreads();
    }
#pragma unroll
    for (int i = 0; i < 4; i++) {
        int m = m0 + tr*4 + i;
        if (m >= M) continue;
#pragma unroll
        for (int j = 0; j < 4; j++) {
            int n = n0 + tc*4 + j;
            if (n >= N) continue;
            long o = (long)m * ldc + n;
            if (accumulate) C[o] += acc[i][j];
            else            C[o]  = acc[i][j];
        }
    }
}

// ---------------- causal depthwise conv (DC=4) + SiLU ----------------------
__global__ void k_conv(const float* __restrict__ z, const float* __restrict__ cw,
                       const float* __restrict__ cb, float* __restrict__ uc)
{
    int idx = blockIdx.x * blockDim.x + threadIdx.x;
    if (idx >= MM*DINN) return;
    int d = idx % DINN;
    int m = idx / DINN;
    int t = m % VV, b = m / VV;
    float acc = cb[d];
#pragma unroll
    for (int h = 0; h < DCC; h++) {
        int tt = t + h - (DCC - 1);
        if (tt >= 0) acc += cw[d*DCC + h] * z[(long)(b*VV + tt)*(2*DINN) + d];
    }
    uc[idx] = acc / (1.f + __expf(-acc));   // silu
}

// ---------------- softplus(delta + bias) in-place ---------------------------
__global__ void k_softplus(float* __restrict__ delta, const float* __restrict__ bias)
{
    int idx = blockIdx.x * blockDim.x + threadIdx.x;
    if (idx >= MM*DINN) return;
    float v = delta[idx] + bias[idx % DINN];
    delta[idx] = fmaxf(v, 0.f) + log1pf(__expf(-fabsf(v)));
}

// ---------------- selective scan over V=30 ---------------------------------
// one thread per (b, d); B/C tiles cached in shared per block (per-b).
__global__ void k_scan(const float* __restrict__ delta, const float* __restrict__ uc,
                       const float* __restrict__ dbl, const float* __restrict__ A_log,
                       const float* __restrict__ Dsk, float* __restrict__ y)
{
    __shared__ float sB[VV][DSS];
    __shared__ float sC[VV][DSS];
    const int chunks = DINN / 256;             // 5
    int b  = blockIdx.x / chunks;
    int dc = blockIdx.x % chunks;
    int d  = dc * 256 + threadIdx.x;

    for (int i = threadIdx.x; i < VV*DSS; i += 256) {
        int t = i / DSS, s = i % DSS;
        const float* row = dbl + (long)(b*VV + t) * DBLW;
        sB[t][s] = row[DTRR + s];
        sC[t][s] = row[DTRR + DSS + s];
    }
    __syncthreads();

    float a[DSS], h[DSS];
#pragma unroll
    for (int s = 0; s < DSS; s++) {
        a[s] = -expf(A_log[(long)d*DSS + s]);
        h[s] = 0.f;
    }
    float dsk = Dsk[d];

    for (int t = 0; t < VV; t++) {
        long m = (long)(b*VV + t);
        float dl = delta[m*DINN + d];
        float uu = uc[m*DINN + d];
        float du = dl * uu;
        float acc = 0.f;
#pragma unroll
        for (int s = 0; s < DSS; s++) {
            float dA = __expf(dl * a[s]);
            h[s] = dA * h[s] + du * sB[t][s];
            acc += h[s] * sC[t][s];
        }
        y[m*DINN + d] = acc + uu * dsk;
    }
}

// ---------------- gate: y2 = y * silu(res) ----------------------------------
__global__ void k_gate(const float* __restrict__ y, const float* __restrict__ z,
                       float* __restrict__ y2)
{
    int idx = blockIdx.x * blockDim.x + threadIdx.x;
    if (idx >= MM*DINN) return;
    int d = idx % DINN;
    int m = idx / DINN;
    float r = z[(long)m*(2*DINN) + DINN + d];
    y2[idx] = y[idx] * (r / (1.f + __expf(-r)));
}

// ---------------- host orchestration ---------------------------------------
static void launch_gemm(const float* A, int lda, const float* W,
                        float* C, int ldc, int M, int N, int K, int accumulate)
{
    dim3 grid((N + 63) / 64, (M + 63) / 64);
    k_sgemm<<<grid, 256>>>(A, lda, W, C, ldc, M, N, K, accumulate);
}

extern "C" void kernel_launch(void* const* d_in, const int* in_sizes, int n_in,
                              void* d_out, int out_size)
{
    const float* x        = (const float*)d_in[0];
    const int*   vs       = (const int*)  d_in[1];
    const float* norm_w   = (const float*)d_in[2];
    const float* in_w     = (const float*)d_in[3];
    const float* conv_w   = (const float*)d_in[4];
    const float* conv_b   = (const float*)d_in[5];
    const float* xp_w     = (const float*)d_in[6];
    const float* dt_w     = (const float*)d_in[7];
    const float* dt_b     = (const float*)d_in[8];
    const float* A_log    = (const float*)d_in[9];
    const float* D_skip   = (const float*)d_in[10];
    const float* out_w    = (const float*)d_in[11];
    const float* norm_f_w = (const float*)d_in[12];
    float* out = (float*)d_out;

    float *hb, *xn, *z, *uc, *dbl, *delta, *y, *y2;
    cudaGetSymbolAddress((void**)&hb,    g_h);
    cudaGetSymbolAddress((void**)&xn,    g_xn);
    cudaGetSymbolAddress((void**)&z,     g_z);
    cudaGetSymbolAddress((void**)&uc,    g_uc);
    cudaGetSymbolAddress((void**)&dbl,   g_dbl);
    cudaGetSymbolAddress((void**)&delta, g_delta);
    cudaGetSymbolAddress((void**)&y,     g_y);
    cudaGetSymbolAddress((void**)&y2,    g_y2);

    const int nD   = MM*DD;
    const int nDIN = MM*DINN;

    // forward circular permute
    k_permute<<<(nD + 255)/256, 256>>>(x, vs, hb, 0);

    for (int i = 0; i < NLL; i++) {
        // RMSNorm
        k_rmsnorm<<<MM, 256>>>(hb, norm_w + (long)i*DD, xn);
        // in_proj: z[M, 2*DIN]
        launch_gemm(xn, DD, in_w + (long)i*2*DINN*DD, z, 2*DINN, MM, 2*DINN, DD, 0);
        // causal depthwise conv + silu
        k_conv<<<(nDIN + 255)/256, 256>>>(z, conv_w + (long)i*DINN*DCC,
                                          conv_b + (long)i*DINN, uc);
        // x_proj: dbl[M, 72]
        launch_gemm(uc, DINN, xp_w + (long)i*DBLW*DINN, dbl, DBLW, MM, DBLW, DINN, 0);
        // dt_proj: delta[M, DIN] from dbl[:, :40]
        launch_gemm(dbl, DBLW, dt_w + (long)i*DINN*DTRR, delta, DINN, MM, DINN, DTRR, 0);
        // softplus(delta + dt_b)
        k_softplus<<<(nDIN + 255)/256, 256>>>(delta, dt_b + (long)i*DINN);
        // selective scan
        k_scan<<<BB*(DINN/256), 256>>>(delta, uc, dbl,
                                       A_log + (long)i*DINN*DSS,
                                       D_skip + (long)i*DINN, y);
        // gate with silu(res)
        k_gate<<<(nDIN + 255)/256, 256>>>(y, z, y2);
        // out_proj, accumulate into residual stream h
        launch_gemm(y2, DINN, out_w + (long)i*DD*DINN, hb, DD, MM, DD, DINN, 1);
    }

    // final RMSNorm + reverse permute
    k_rmsnorm<<<MM, 256>>>(hb, norm_f_w, xn);
    k_permute<<<(nD + 255)/256, 256>>>(xn, vs, out, 1);
}

// round 3
// speedup vs baseline: 1.9835x; 1.9835x over previous
#include <cuda_runtime.h>
#include <cuda_bf16.h>
#include <cstdint>
#include <math.h>

#define BB   64
#define VV   30
#define DD   640
#define DINN 1280
#define DSS  16
#define DTRR 40
#define DCC  4
#define NLL  4
#define MM   (BB*VV)          // 1920
#define DBLW (DTRR + 2*DSS)   // 72

// ---------------- scratch (device globals; no runtime allocation) ----------
__device__ float g_h[MM*DD];
__device__ float g_xn[MM*DD];
__device__ float g_z[MM*2*DINN];     // in_proj output: [:,0:DIN]=u, [:,DIN:2DIN]=res
__device__ float g_uc[MM*DINN];      // conv+silu output
__device__ float g_dbl[MM*DBLW];     // x_proj output (delta_raw | B | C)
__device__ float g_delta[MM*DINN];   // dt_proj output (raw; softplus fused in scan)
__device__ float g_y2[MM*DINN];      // gated scan output

// ======================= mma.sync bf16 3-product GEMM =======================
// C[M,N] = A[M,K] * W[N,K]^T (+C).
// CTA tile 128x128, 256 threads (8 warps as 2x4), warp tile 64x32.
// K in chunks of 32; fp32 -> (bf16 hi, bf16 lo) split in smem; per k16 step
// issue 3 mma products per atom: hi*hi + lo*hi + hi*lo (drop lo*lo ~2^-18).

#define PADK 36   // 32 bf16 + 4 pad (avoids LDS bank conflicts)

__device__ __forceinline__ uint32_t lds_u32(const __nv_bfloat16* p) {
    return *reinterpret_cast<const uint32_t*>(p);
}

__device__ __forceinline__ void mma_bf16(float* c, const uint32_t* a, const uint32_t* b) {
    asm volatile(
        "mma.sync.aligned.m16n8k16.row.col.f32.bf16.bf16.f32 "
        "{%0,%1,%2,%3}, {%4,%5,%6,%7}, {%8,%9}, {%0,%1,%2,%3};"
        : "+f"(c[0]), "+f"(c[1]), "+f"(c[2]), "+f"(c[3])
        : "r"(a[0]), "r"(a[1]), "r"(a[2]), "r"(a[3]), "r"(b[0]), "r"(b[1]));
}

__device__ __forceinline__ void split4_store(float4 v, __nv_bfloat16* hi,
                                             __nv_bfloat16* lo)
{
    __nv_bfloat162 h01 = __float22bfloat162_rn(make_float2(v.x, v.y));
    __nv_bfloat162 h23 = __float22bfloat162_rn(make_float2(v.z, v.w));
    float2 r01 = make_float2(v.x - __bfloat162float(h01.x),
                             v.y - __bfloat162float(h01.y));
    float2 r23 = make_float2(v.z - __bfloat162float(h23.x),
                             v.w - __bfloat162float(h23.y));
    __nv_bfloat162 l01 = __float22bfloat162_rn(r01);
    __nv_bfloat162 l23 = __float22bfloat162_rn(r23);
    uint2 hv, lv;
    hv.x = *reinterpret_cast<uint32_t*>(&h01);
    hv.y = *reinterpret_cast<uint32_t*>(&h23);
    lv.x = *reinterpret_cast<uint32_t*>(&l01);
    lv.y = *reinterpret_cast<uint32_t*>(&l23);
    *reinterpret_cast<uint2*>(hi) = hv;
    *reinterpret_cast<uint2*>(lo) = lv;
}

__global__ void __launch_bounds__(256)
k_mma_gemm(const float* __restrict__ A, int lda,
           const float* __restrict__ W,
           float* __restrict__ C, int ldc,
           int K, int accumulate)
{
    __shared__ __nv_bfloat16 sAh[128][PADK];
    __shared__ __nv_bfloat16 sAl[128][PADK];
    __shared__ __nv_bfloat16 sWh[128][PADK];
    __shared__ __nv_bfloat16 sWl[128][PADK];

    int tid  = threadIdx.x;
    int lane = tid & 31, wid = tid >> 5;
    int wm = wid >> 2, wn = wid & 3;          // warp grid 2x4
    int m0 = blockIdx.y * 128, n0 = blockIdx.x * 128;
    int lq = lane & 3, lr4 = lane >> 2;

    // loader mapping: 4 rows per thread, 4 consecutive floats each
    int lrow = tid >> 3;          // 0..31
    int lcol = (tid & 7) * 4;     // 0..28

    float acc[4][4][4];
#pragma unroll
    for (int i = 0; i < 4; i++)
#pragma unroll
        for (int j = 0; j < 4; j++)
#pragma unroll
            for (int q = 0; q < 4; q++) acc[i][j][q] = 0.f;

    const int nch = K / 32;
    float4 pa[4], pw[4];
#pragma unroll
    for (int i = 0; i < 4; i++) {
        pa[i] = *reinterpret_cast<const float4*>(&A[(size_t)(m0 + lrow + i*32)*lda + lcol]);
        pw[i] = *reinterpret_cast<const float4*>(&W[(size_t)(n0 + lrow + i*32)*K   + lcol]);
    }

    for (int ch = 0; ch < nch; ch++) {
#pragma unroll
        for (int i = 0; i < 4; i++) {
            split4_store(pa[i], &sAh[lrow + i*32][lcol], &sAl[lrow + i*32][lcol]);
            split4_store(pw[i], &sWh[lrow + i*32][lcol], &sWl[lrow + i*32][lcol]);
        }
        __syncthreads();
        if (ch + 1 < nch) {
            int k0 = (ch + 1) * 32 + lcol;
#pragma unroll
            for (int i = 0; i < 4; i++) {
                pa[i] = *reinterpret_cast<const float4*>(&A[(size_t)(m0 + lrow + i*32)*lda + k0]);
                pw[i] = *reinterpret_cast<const float4*>(&W[(size_t)(n0 + lrow + i*32)*K   + k0]);
            }
        }
#pragma unroll
        for (int ks = 0; ks < 2; ks++) {
            int c0 = ks*16 + lq*2;
            uint32_t ah[4][4], al[4][4], bh[4][2], bl[4][2];
#pragma unroll
            for (int am = 0; am < 4; am++) {
                int r0 = wm*64 + am*16 + lr4;
                ah[am][0] = lds_u32(&sAh[r0    ][c0  ]);
                ah[am][1] = lds_u32(&sAh[r0 + 8][c0  ]);
                ah[am][2] = lds_u32(&sAh[r0    ][c0+8]);
                ah[am][3] = lds_u32(&sAh[r0 + 8][c0+8]);
                al[am][0] = lds_u32(&sAl[r0    ][c0  ]);
                al[am][1] = lds_u32(&sAl[r0 + 8][c0  ]);
                al[am][2] = lds_u32(&sAl[r0    ][c0+8]);
                al[am][3] = lds_u32(&sAl[r0 + 8][c0+8]);
            }
#pragma unroll
            for (int bn = 0; bn < 4; bn++) {
                int n = wn*32 + bn*8 + lr4;
                bh[bn][0] = lds_u32(&sWh[n][c0  ]);
                bh[bn][1] = lds_u32(&sWh[n][c0+8]);
                bl[bn][0] = lds_u32(&sWl[n][c0  ]);
                bl[bn][1] = lds_u32(&sWl[n][c0+8]);
            }
#pragma unroll
            for (int am = 0; am < 4; am++)
#pragma unroll
                for (int bn = 0; bn < 4; bn++) {
                    mma_bf16(acc[am][bn], ah[am], bh[bn]);
                    mma_bf16(acc[am][bn], al[am], bh[bn]);
                    mma_bf16(acc[am][bn], ah[am], bl[bn]);
                }
        }
        __syncthreads();
    }

    // epilogue
#pragma unroll
    for (int am = 0; am < 4; am++) {
        int row = m0 + wm*64 + am*16 + lr4;
#pragma unroll
        for (int bn = 0; bn < 4; bn++) {
            int col = n0 + wn*32 + bn*8 + lq*2;
            float* p0 = &C[(size_t)row*ldc + col];
            float* p1 = &C[(size_t)(row + 8)*ldc + col];
            if (accumulate) {
                float2 o0 = *reinterpret_cast<float2*>(p0);
                float2 o1 = *reinterpret_cast<float2*>(p1);
                o0.x += acc[am][bn][0]; o0.y += acc[am][bn][1];
                o1.x += acc[am][bn][2]; o1.y += acc[am][bn][3];
                *reinterpret_cast<float2*>(p0) = o0;
                *reinterpret_cast<float2*>(p1) = o1;
            } else {
                *reinterpret_cast<float2*>(p0) = make_float2(acc[am][bn][0], acc[am][bn][1]);
                *reinterpret_cast<float2*>(p1) = make_float2(acc[am][bn][2], acc[am][bn][3]);
            }
        }
    }
}

// ---------------- permute (fwd: rev=0, reverse: rev=1) ---------------------
__global__ void k_permute(const float* __restrict__ in, const int* __restrict__ vs,
                          float* __restrict__ out, int rev)
{
    int idx = blockIdx.x * blockDim.x + threadIdx.x;
    if (idx >= MM*DD) return;
    int d = idx % DD;
    int m = idx / DD;
    int t = m % VV, b = m / VV;
    int v = vs[b];
    int src = rev ? ((t + v) % VV) : ((t + VV - v) % VV);
    out[idx] = in[(b*VV + src)*DD + d];
}

// ---------------- RMSNorm over D=640, one block per row --------------------
__global__ void k_rmsnorm(const float* __restrict__ in, const float* __restrict__ w,
                          float* __restrict__ out)
{
    int m = blockIdx.x;
    const float* row = in + m*DD;
    float ss = 0.f;
    for (int i = threadIdx.x; i < DD; i += blockDim.x) { float v = row[i]; ss += v*v; }
    __shared__ float red[32];
    for (int o = 16; o; o >>= 1) ss += __shfl_xor_sync(0xffffffffu, ss, o);
    if ((threadIdx.x & 31) == 0) red[threadIdx.x >> 5] = ss;
    __syncthreads();
    if (threadIdx.x < 32) {
        float v = (threadIdx.x < (blockDim.x >> 5)) ? red[threadIdx.x] : 0.f;
        for (int o = 16; o; o >>= 1) v += __shfl_xor_sync(0xffffffffu, v, o);
        red[threadIdx.x] = v;
    }
    __syncthreads();
    float scale = rsqrtf(red[0] * (1.f/DD) + 1e-5f);
    for (int i = threadIdx.x; i < DD; i += blockDim.x)
        out[m*DD + i] = row[i] * scale * w[i];
}

// ---------------- generic SGEMM (small GEMMs): C = A * W^T ------------------
__global__ void k_sgemm(const float* __restrict__ A, int lda,
                        const float* __restrict__ W,
                        float* __restrict__ C, int ldc,
                        int M, int N, int K, int accumulate)
{
    __shared__ float As[16][64];
    __shared__ float Ws[16][64];
    int tid = threadIdx.x;
    int m0 = blockIdx.y * 64;
    int n0 = blockIdx.x * 64;
    int tr = tid >> 4;
    int tc = tid & 15;
    int lr = tid >> 2;
    int lk = (tid & 3) * 4;

    float acc[4][4];
#pragma unroll
    for (int i = 0; i < 4; i++)
#pragma unroll
        for (int j = 0; j < 4; j++) acc[i][j] = 0.f;

    for (int k0 = 0; k0 < K; k0 += 16) {
        int am = m0 + lr;
        int wn = n0 + lr;
#pragma unroll
        for (int j = 0; j < 4; j++) {
            int k = k0 + lk + j;
            As[lk + j][lr] = (k < K && am < M) ? A[(long)am * lda + k] : 0.f;
            Ws[lk + j][lr] = (k < K && wn < N) ? W[(long)wn * K   + k] : 0.f;
        }
        __syncthreads();
#pragma unroll
        for (int kk = 0; kk < 16; kk++) {
            float av[4], wv[4];
#pragma unroll
            for (int i = 0; i < 4; i++) av[i] = As[kk][tr*4 + i];
#pragma unroll
            for (int j = 0; j < 4; j++) wv[j] = Ws[kk][tc*4 + j];
#pragma unroll
            for (int i = 0; i < 4; i++)
#pragma unroll
                for (int j = 0; j < 4; j++) acc[i][j] += av[i] * wv[j];
        }
        __syncthreads();
    }
#pragma unroll
    for (int i = 0; i < 4; i++) {
        int m = m0 + tr*4 + i;
        if (m >= M) continue;
#pragma unroll
        for (int j = 0; j < 4; j++) {
            int n = n0 + tc*4 + j;
            if (n >= N) continue;
            long o = (long)m * ldc + n;
            if (accumulate) C[o] += acc[i][j];
            else            C[o]  = acc[i][j];
        }
    }
}

// ---------------- causal depthwise conv (DC=4) + SiLU ----------------------
__global__ void k_conv(const float* __restrict__ z, const float* __restrict__ cw,
                       const float* __restrict__ cb, float* __restrict__ uc)
{
    int idx = blockIdx.x * blockDim.x + threadIdx.x;
    if (idx >= MM*DINN) return;
    int d = idx % DINN;
    int m = idx / DINN;
    int t = m % VV, b = m / VV;
    float acc = cb[d];
#pragma unroll
    for (int h = 0; h < DCC; h++) {
        int tt = t + h - (DCC - 1);
        if (tt >= 0) acc += cw[d*DCC + h] * z[(long)(b*VV + tt)*(2*DINN) + d];
    }
    uc[idx] = acc / (1.f + __expf(-acc));   // silu
}

// ---------------- selective scan (fused softplus + output gate) ------------
__global__ void k_scan(const float* __restrict__ delta_raw,
                       const float* __restrict__ dt_b,
                       const float* __restrict__ uc,
                       const float* __restrict__ z,
                       const float* __restrict__ dbl, const float* __restrict__ A_log,
                       const float* __restrict__ Dsk, float* __restrict__ y2)
{
    __shared__ float sB[VV][DSS];
    __shared__ float sC[VV][DSS];
    const int chunks = DINN / 256;             // 5
    int b  = blockIdx.x / chunks;
    int dc = blockIdx.x % chunks;
    int d  = dc * 256 + threadIdx.x;

    for (int i = threadIdx.x; i < VV*DSS; i += 256) {
        int t = i / DSS, s = i % DSS;
        const float* row = dbl + (long)(b*VV + t) * DBLW;
        sB[t][s] = row[DTRR + s];
        sC[t][s] = row[DTRR + DSS + s];
    }
    __syncthreads();

    float a[DSS], h[DSS];
#pragma unroll
    for (int s = 0; s < DSS; s++) {
        a[s] = -expf(A_log[(long)d*DSS + s]);
        h[s] = 0.f;
    }
    float dsk = Dsk[d];
    float bias = dt_b[d];

    for (int t = 0; t < VV; t++) {
        long m = (long)(b*VV + t);
        float dv = delta_raw[m*DINN + d] + bias;
        float dl = fmaxf(dv, 0.f) + log1pf(__expf(-fabsf(dv)));   // softplus
        float uu = uc[m*DINN + d];
        float du = dl * uu;
        float acc = 0.f;
#pragma unroll
        for (int s = 0; s < DSS; s++) {
            float dA = __expf(dl * a[s]);
            h[s] = dA * h[s] + du * sB[t][s];
            acc += h[s] * sC[t][s];
        }
        float r = z[m*(2*DINN) + DINN + d];
        y2[m*DINN + d] = (acc + uu * dsk) * (r / (1.f + __expf(-r)));
    }
}

// ---------------- host orchestration ---------------------------------------
static void launch_gemm_small(const float* A, int lda, const float* W,
                              float* C, int ldc, int M, int N, int K, int accumulate)
{
    dim3 grid((N + 63) / 64, (M + 63) / 64);
    k_sgemm<<<grid, 256>>>(A, lda, W, C, ldc, M, N, K, accumulate);
}

static void launch_gemm_mma(const float* A, int lda, const float* W,
                            float* C, int ldc, int M, int N, int K, int accumulate)
{
    dim3 grid(N / 128, M / 128);
    k_mma_gemm<<<grid, 256>>>(A, lda, W, C, ldc, K, accumulate);
}

extern "C" void kernel_launch(void* const* d_in, const int* in_sizes, int n_in,
                              void* d_out, int out_size)
{
    const float* x        = (const float*)d_in[0];
    const int*   vs       = (const int*)  d_in[1];
    const float* norm_w   = (const float*)d_in[2];
    const float* in_w     = (const float*)d_in[3];
    const float* conv_w   = (const float*)d_in[4];
    const float* conv_b   = (const float*)d_in[5];
    const float* xp_w     = (const float*)d_in[6];
    const float* dt_w     = (const float*)d_in[7];
    const float* dt_b     = (const float*)d_in[8];
    const float* A_log    = (const float*)d_in[9];
    const float* D_skip   = (const float*)d_in[10];
    const float* out_w    = (const float*)d_in[11];
    const float* norm_f_w = (const float*)d_in[12];
    float* out = (float*)d_out;

    float *hb, *xn, *z, *uc, *dbl, *delta, *y2;
    cudaGetSymbolAddress((void**)&hb,    g_h);
    cudaGetSymbolAddress((void**)&xn,    g_xn);
    cudaGetSymbolAddress((void**)&z,     g_z);
    cudaGetSymbolAddress((void**)&uc,    g_uc);
    cudaGetSymbolAddress((void**)&dbl,   g_dbl);
    cudaGetSymbolAddress((void**)&delta, g_delta);
    cudaGetSymbolAddress((void**)&y2,    g_y2);

    const int nD   = MM*DD;
    const int nDIN = MM*DINN;

    // forward circular permute
    k_permute<<<(nD + 255)/256, 256>>>(x, vs, hb, 0);

    for (int i = 0; i < NLL; i++) {
        // RMSNorm
        k_rmsnorm<<<MM, 256>>>(hb, norm_w + (long)i*DD, xn);
        // in_proj: z[M, 2*DIN]  (tensor cores via mma.sync, bf16 3-product)
        launch_gemm_mma(xn, DD, in_w + (long)i*2*DINN*DD, z, 2*DINN, MM, 2*DINN, DD, 0);
        // causal depthwise conv + silu
        k_conv<<<(nDIN + 255)/256, 256>>>(z, conv_w + (long)i*DINN*DCC,
                                          conv_b + (long)i*DINN, uc);
        // x_proj: dbl[M, 72]
        launch_gemm_small(uc, DINN, xp_w + (long)i*DBLW*DINN, dbl, DBLW, MM, DBLW, DINN, 0);
        // dt_proj: delta[M, DIN] from dbl[:, :40]
        launch_gemm_small(dbl, DBLW, dt_w + (long)i*DINN*DTRR, delta, DINN, MM, DINN, DTRR, 0);
        // selective scan (softplus + gate fused)
        k_scan<<<BB*(DINN/256), 256>>>(delta, dt_b + (long)i*DINN, uc, z, dbl,
                                       A_log + (long)i*DINN*DSS,
                                       D_skip + (long)i*DINN, y2);
        // out_proj, accumulate into residual stream h
        launch_gemm_mma(y2, DINN, out_w + (long)i*DD*DINN, hb, DD, MM, DD, DINN, 1);
    }

    // final RMSNorm + reverse permute
    k_rmsnorm<<<MM, 256>>>(hb, norm_f_w, xn);
    k_permute<<<(nD + 255)/256, 256>>>(xn, vs, out, 1);
}

// round 4
// speedup vs baseline: 2.2401x; 1.1294x over previous
#include <cuda_runtime.h>
#include <cuda_fp16.h>
#include <cstdint>
#include <math.h>

#define BB   64
#define VV   30
#define DD   640
#define DINN 1280
#define DSS  16
#define DTRR 40
#define DCC  4
#define NLL  4
#define MM   (BB*VV)          // 1920
#define DBLW (DTRR + 2*DSS)   // 72

// ---------------- scratch (device globals; no runtime allocation) ----------
__device__ float g_h[MM*DD];
__device__ float g_xn[MM*DD];
__device__ float g_z[MM*2*DINN];
__device__ float g_uc[MM*DINN];
__device__ float g_dbl[MM*DBLW];
__device__ float g_delta[MM*DINN];
// fp16 hi/lo planes
__device__ __half g_ah[MM*DINN];
__device__ __half g_al[MM*DINN];
__device__ __half g_wh_in[NLL*2*DINN*DD];
__device__ __half g_wl_in[NLL*2*DINN*DD];
__device__ __half g_wh_out[NLL*DD*DINN];
__device__ __half g_wl_out[NLL*DD*DINN];

// ======================= low-level helpers ==================================
__device__ __forceinline__ uint32_t smem_u32(const void* p) {
    uint32_t a;
    asm("{ .reg .u64 t; cvta.to.shared.u64 t, %1; cvt.u32.u64 %0, t; }"
        : "=r"(a) : "l"(p));
    return a;
}
__device__ __forceinline__ void cp_async16(uint32_t dst, const void* src) {
    asm volatile("cp.async.cg.shared.global [%0], [%1], 16;" :: "r"(dst), "l"(src));
}
#define CP_COMMIT() asm volatile("cp.async.commit_group;" ::: "memory")
#define CP_WAIT(N)  asm volatile("cp.async.wait_group %0;" :: "n"(N) : "memory")
#define LDSM_X4(R, addr) \
    asm volatile("ldmatrix.sync.aligned.m8n8.x4.shared.b16 {%0,%1,%2,%3}, [%4];" \
        : "=r"((R)[0]), "=r"((R)[1]), "=r"((R)[2]), "=r"((R)[3]) : "r"(addr))

__device__ __forceinline__ void mma_f16(float* c, const uint32_t* a, const uint32_t* b) {
    asm volatile(
        "mma.sync.aligned.m16n8k16.row.col.f32.f16.f16.f32 "
        "{%0,%1,%2,%3}, {%4,%5,%6,%7}, {%8,%9}, {%0,%1,%2,%3};"
        : "+f"(c[0]), "+f"(c[1]), "+f"(c[2]), "+f"(c[3])
        : "r"(a[0]), "r"(a[1]), "r"(a[2]), "r"(a[3]), "r"(b[0]), "r"(b[1]));
}

// ======================= fp16 hi/lo 3-product HGEMM =========================
// C[M,N] (+)= A[M,K] * W[N,K]^T ; A,W given as fp16 hi/lo planes.
// CTA tile 128 x TN, 256 threads, BK=32, STAGES-deep cp.async pipeline.
#define BKH    32
#define RP     40     // smem row stride in halves (80B) -> ldmatrix conflict-free

template<int TN, int WMW, int WNW, int MAT, int NAT, int STAGES>
__global__ void __launch_bounds__(256)
k_hgemm(const __half* __restrict__ Ah, const __half* __restrict__ Al, int lda,
        const __half* __restrict__ Wh, const __half* __restrict__ Wl,
        float* __restrict__ C, int ldc, int K, int accumulate)
{
    extern __shared__ char sm[];
    constexpr int PLA   = 128 * RP * 2;          // A plane bytes (10240)
    constexpr int PLB   = TN  * RP * 2;          // W plane bytes
    constexpr int STAGE = 2*PLA + 2*PLB;

    const int tid = threadIdx.x, lane = tid & 31, wid = tid >> 5;
    const int wm = wid / WNW, wn = wid % WNW;
    const int m0 = blockIdx.y * 128, n0 = blockIdx.x * TN;
    const uint32_t sb = smem_u32(sm);

    // ldmatrix per-lane addressing
    const int g  = lane >> 3, lr = lane & 7;
    const int a_row = ((g & 1) ? 8 : 0) + lr;    // + warp/atom base
    const int a_kg  = (g >> 1);                  // + ks*2
    const int b_row = ((g >> 1) ? 8 : 0) + lr;
    const int b_kg  = (g & 1);

    float acc[MAT][NAT][4];
#pragma unroll
    for (int i = 0; i < MAT; i++)
#pragma unroll
        for (int j = 0; j < NAT; j++)
#pragma unroll
            for (int q = 0; q < 4; q++) acc[i][j][q] = 0.f;

    const int nch = K / BKH;

    auto load_stage = [&](int st, int ch) {
        const uint32_t sa = sb + st * STAGE;
        const int kbase = ch * BKH;
#pragma unroll
        for (int c = tid; c < 512; c += 256) {           // A: 128 rows x 4 grp
            int r = c >> 2, kg = c & 3;
            size_t go = (size_t)(m0 + r) * lda + kbase + kg * 8;
            uint32_t so = (uint32_t)(r * (RP*2) + kg * 16);
            cp_async16(sa + so,        Ah + go);
            cp_async16(sa + PLA + so,  Al + go);
        }
#pragma unroll
        for (int c = tid; c < TN*4; c += 256) {          // W: TN rows x 4 grp
            int r = c >> 2, kg = c & 3;
            size_t go = (size_t)(n0 + r) * K + kbase + kg * 8;
            uint32_t so = (uint32_t)(r * (RP*2) + kg * 16);
            cp_async16(sa + 2*PLA + so,        Wh + go);
            cp_async16(sa + 2*PLA + PLB + so,  Wl + go);
        }
        CP_COMMIT();
    };

#pragma unroll
    for (int s = 0; s < STAGES - 1; s++) load_stage(s, s);

    for (int ch = 0; ch < nch; ch++) {
        int pre = ch + STAGES - 1;
        if (pre < nch) load_stage(pre % STAGES, pre);
        else           CP_COMMIT();
        CP_WAIT(STAGES - 2);
        __syncthreads();

        const uint32_t sa = sb + (ch % STAGES) * STAGE;
#pragma unroll
        for (int ks = 0; ks < 2; ks++) {
            uint32_t ah[MAT][4], al[MAT][4], bh[NAT][2], bl[NAT][2];
#pragma unroll
            for (int am = 0; am < MAT; am++) {
                int row = wm * (MAT*16) + am*16 + a_row;
                uint32_t ad = sa + row * (RP*2) + (ks*2 + a_kg) * 16;
                LDSM_X4(ah[am], ad);
                LDSM_X4(al[am], ad + PLA);
            }
#pragma unroll
            for (int p = 0; p < NAT/2; p++) {
                int row = wn * (NAT*8) + p*16 + b_row;
                uint32_t ad = sa + 2*PLA + row * (RP*2) + (ks*2 + b_kg) * 16;
                uint32_t th[4], tl[4];
                LDSM_X4(th, ad);
                LDSM_X4(tl, ad + PLB);
                bh[2*p][0]=th[0]; bh[2*p][1]=th[1]; bh[2*p+1][0]=th[2]; bh[2*p+1][1]=th[3];
                bl[2*p][0]=tl[0]; bl[2*p][1]=tl[1]; bl[2*p+1][0]=tl[2]; bl[2*p+1][1]=tl[3];
            }
#pragma unroll
            for (int am = 0; am < MAT; am++)
#pragma unroll
                for (int bn = 0; bn < NAT; bn++) {
                    mma_f16(acc[am][bn], ah[am], bh[bn]);
                    mma_f16(acc[am][bn], al[am], bh[bn]);
                    mma_f16(acc[am][bn], ah[am], bl[bn]);
                }
        }
        __syncthreads();
    }

    // epilogue
    const int lq = lane & 3, lr4 = lane >> 2;
#pragma unroll
    for (int am = 0; am < MAT; am++) {
        int row = m0 + wm*(MAT*16) + am*16 + lr4;
#pragma unroll
        for (int bn = 0; bn < NAT; bn++) {
            int col = n0 + wn*(NAT*8) + bn*8 + lq*2;
            float* p0 = &C[(size_t)row       * ldc + col];
            float* p1 = &C[(size_t)(row + 8) * ldc + col];
            if (accumulate) {
                float2 o0 = *reinterpret_cast<float2*>(p0);
                float2 o1 = *reinterpret_cast<float2*>(p1);
                o0.x += acc[am][bn][0]; o0.y += acc[am][bn][1];
                o1.x += acc[am][bn][2]; o1.y += acc[am][bn][3];
                *reinterpret_cast<float2*>(p0) = o0;
                *reinterpret_cast<float2*>(p1) = o1;
            } else {
                *reinterpret_cast<float2*>(p0) = make_float2(acc[am][bn][0], acc[am][bn][1]);
                *reinterpret_cast<float2*>(p1) = make_float2(acc[am][bn][2], acc[am][bn][3]);
            }
        }
    }
}

// ---------------- fp32 -> fp16 hi/lo split (for weights) --------------------
__global__ void k_split(const float* __restrict__ in, __half* __restrict__ hi,
                        __half* __restrict__ lo, int n4)
{
    int i = blockIdx.x * blockDim.x + threadIdx.x;
    if (i >= n4) return;
    float4 v = reinterpret_cast<const float4*>(in)[i];
    __half h0 = __float2half_rn(v.x), h1 = __float2half_rn(v.y);
    __half h2 = __float2half_rn(v.z), h3 = __float2half_rn(v.w);
    __half l0 = __float2half_rn(v.x - __half2float(h0));
    __half l1 = __float2half_rn(v.y - __half2float(h1));
    __half l2 = __float2half_rn(v.z - __half2float(h2));
    __half l3 = __float2half_rn(v.w - __half2float(h3));
    reinterpret_cast<__half2*>(hi)[2*i  ] = __halves2half2(h0, h1);
    reinterpret_cast<__half2*>(hi)[2*i+1] = __halves2half2(h2, h3);
    reinterpret_cast<__half2*>(lo)[2*i  ] = __halves2half2(l0, l1);
    reinterpret_cast<__half2*>(lo)[2*i+1] = __halves2half2(l2, l3);
}

// ---------------- permute ---------------------------------------------------
__global__ void k_permute(const float* __restrict__ in, const int* __restrict__ vs,
                          float* __restrict__ out, int rev)
{
    int idx = blockIdx.x * blockDim.x + threadIdx.x;
    if (idx >= MM*DD) return;
    int d = idx % DD;
    int m = idx / DD;
    int t = m % VV, b = m / VV;
    int v = vs[b];
    int src = rev ? ((t + v) % VV) : ((t + VV - v) % VV);
    out[idx] = in[(b*VV + src)*DD + d];
}

// ---------------- RMSNorm: fp32 out ------------------------------------------
__device__ __forceinline__ float rms_scale(const float* row, int tid, int bdim)
{
    float ss = 0.f;
    for (int i = tid; i < DD; i += bdim) { float v = row[i]; ss += v*v; }
    __shared__ float red[32];
    for (int o = 16; o; o >>= 1) ss += __shfl_xor_sync(0xffffffffu, ss, o);
    if ((tid & 31) == 0) red[tid >> 5] = ss;
    __syncthreads();
    if (tid < 32) {
        float v = (tid < (bdim >> 5)) ? red[tid] : 0.f;
        for (int o = 16; o; o >>= 1) v += __shfl_xor_sync(0xffffffffu, v, o);
        red[tid] = v;
    }
    __syncthreads();
    return rsqrtf(red[0] * (1.f/DD) + 1e-5f);
}

__global__ void k_rmsnorm(const float* __restrict__ in, const float* __restrict__ w,
                          float* __restrict__ out)
{
    int m = blockIdx.x;
    const float* row = in + m*DD;
    float scale = rms_scale(row, threadIdx.x, blockDim.x);
    for (int i = threadIdx.x; i < DD; i += blockDim.x)
        out[m*DD + i] = row[i] * scale * w[i];
}

// ---------------- RMSNorm emitting fp16 hi/lo planes -------------------------
__global__ void k_rmsnorm_split(const float* __restrict__ in, const float* __restrict__ w,
                                __half* __restrict__ oh, __half* __restrict__ ol)
{
    int m = blockIdx.x;
    const float* row = in + m*DD;
    float scale = rms_scale(row, threadIdx.x, blockDim.x);
    for (int i = threadIdx.x; i < DD; i += blockDim.x) {
        float o = row[i] * scale * w[i];
        __half h = __float2half_rn(o);
        oh[m*DD + i] = h;
        ol[m*DD + i] = __float2half_rn(o - __half2float(h));
    }
}

// ---------------- generic SGEMM (small GEMMs) --------------------------------
__global__ void k_sgemm(const float* __restrict__ A, int lda,
                        const float* __restrict__ W,
                        float* __restrict__ C, int ldc,
                        int M, int N, int K, int accumulate)
{
    __shared__ float As[16][64];
    __shared__ float Ws[16][64];
    int tid = threadIdx.x;
    int m0 = blockIdx.y * 64;
    int n0 = blockIdx.x * 64;
    int tr = tid >> 4;
    int tc = tid & 15;
    int lr = tid >> 2;
    int lk = (tid & 3) * 4;

    float acc[4][4];
#pragma unroll
    for (int i = 0; i < 4; i++)
#pragma unroll
        for (int j = 0; j < 4; j++) acc[i][j] = 0.f;

    for (int k0 = 0; k0 < K; k0 += 16) {
        int am = m0 + lr;
        int wn = n0 + lr;
#pragma unroll
        for (int j = 0; j < 4; j++) {
            int k = k0 + lk + j;
            As[lk + j][lr] = (k < K && am < M) ? A[(long)am * lda + k] : 0.f;
            Ws[lk + j][lr] = (k < K && wn < N) ? W[(long)wn * K   + k] : 0.f;
        }
        __syncthreads();
#pragma unroll
        for (int kk = 0; kk < 16; kk++) {
            float av[4], wv[4];
#pragma unroll
            for (int i = 0; i < 4; i++) av[i] = As[kk][tr*4 + i];
#pragma unroll
            for (int j = 0; j < 4; j++) wv[j] = Ws[kk][tc*4 + j];
#pragma unroll
            for (int i = 0; i < 4; i++)
#pragma unroll
                for (int j = 0; j < 4; j++) acc[i][j] += av[i] * wv[j];
        }
        __syncthreads();
    }
#pragma unroll
    for (int i = 0; i < 4; i++) {
        int m = m0 + tr*4 + i;
        if (m >= M) continue;
#pragma unroll
        for (int j = 0; j < 4; j++) {
            int n = n0 + tc*4 + j;
            if (n >= N) continue;
            long o = (long)m * ldc + n;
            if (accumulate) C[o] += acc[i][j];
            else            C[o]  = acc[i][j];
        }
    }
}

// ---------------- causal depthwise conv (DC=4) + SiLU ------------------------
__global__ void k_conv(const float* __restrict__ z, const float* __restrict__ cw,
                       const float* __restrict__ cb, float* __restrict__ uc)
{
    int idx = blockIdx.x * blockDim.x + threadIdx.x;
    if (idx >= MM*DINN) return;
    int d = idx % DINN;
    int m = idx / DINN;
    int t = m % VV, b = m / VV;
    float acc = cb[d];
#pragma unroll
    for (int h = 0; h < DCC; h++) {
        int tt = t + h - (DCC - 1);
        if (tt >= 0) acc += cw[d*DCC + h] * z[(long)(b*VV + tt)*(2*DINN) + d];
    }
    uc[idx] = acc / (1.f + __expf(-acc));
}

// ---------------- selective scan (softplus + gate fused; fp16 plane out) ----
__global__ void k_scan(const float* __restrict__ delta_raw,
                       const float* __restrict__ dt_b,
                       const float* __restrict__ uc,
                       const float* __restrict__ z,
                       const float* __restrict__ dbl, const float* __restrict__ A_log,
                       const float* __restrict__ Dsk,
                       __half* __restrict__ yh, __half* __restrict__ yl)
{
    __shared__ float sB[VV][DSS];
    __shared__ float sC[VV][DSS];
    const int chunks = DINN / 256;
    int b  = blockIdx.x / chunks;
    int dc = blockIdx.x % chunks;
    int d  = dc * 256 + threadIdx.x;

    for (int i = threadIdx.x; i < VV*DSS; i += 256) {
        int t = i / DSS, s = i % DSS;
        const float* row = dbl + (long)(b*VV + t) * DBLW;
        sB[t][s] = row[DTRR + s];
        sC[t][s] = row[DTRR + DSS + s];
    }
    __syncthreads();

    float a[DSS], h[DSS];
#pragma unroll
    for (int s = 0; s < DSS; s++) {
        a[s] = -expf(A_log[(long)d*DSS + s]);
        h[s] = 0.f;
    }
    float dsk = Dsk[d];
    float bias = dt_b[d];

    for (int t = 0; t < VV; t++) {
        long m = (long)(b*VV + t);
        float dv = delta_raw[m*DINN + d] + bias;
        float dl = fmaxf(dv, 0.f) + log1pf(__expf(-fabsf(dv)));
        float uu = uc[m*DINN + d];
        float du = dl * uu;
        float acc = 0.f;
#pragma unroll
        for (int s = 0; s < DSS; s++) {
            float dA = __expf(dl * a[s]);
            h[s] = dA * h[s] + du * sB[t][s];
            acc += h[s] * sC[t][s];
        }
        float r = z[m*(2*DINN) + DINN + d];
        float yv = (acc + uu * dsk) * (r / (1.f + __expf(-r)));
        __half hh = __float2half_rn(yv);
        yh[m*DINN + d] = hh;
        yl[m*DINN + d] = __float2half_rn(yv - __half2float(hh));
    }
}

// ---------------- host orchestration ----------------------------------------
#define SMEM128 (4 * (2*128*RP*2 + 2*128*RP*2))   // 4 stages, TN=128: 163840
#define SMEM64  (4 * (2*128*RP*2 + 2*64*RP*2))    // 4 stages, TN=64 : 122880

static void launch_gemm_small(const float* A, int lda, const float* W,
                              float* C, int ldc, int M, int N, int K, int accumulate)
{
    dim3 grid((N + 63) / 64, (M + 63) / 64);
    k_sgemm<<<grid, 256>>>(A, lda, W, C, ldc, M, N, K, accumulate);
}

extern "C" void kernel_launch(void* const* d_in, const int* in_sizes, int n_in,
                              void* d_out, int out_size)
{
    const float* x        = (const float*)d_in[0];
    const int*   vs       = (const int*)  d_in[1];
    const float* norm_w   = (const float*)d_in[2];
    const float* in_w     = (const float*)d_in[3];
    const float* conv_w   = (const float*)d_in[4];
    const float* conv_b   = (const float*)d_in[5];
    const float* xp_w     = (const float*)d_in[6];
    const float* dt_w     = (const float*)d_in[7];
    const float* dt_b     = (const float*)d_in[8];
    const float* A_log    = (const float*)d_in[9];
    const float* D_skip   = (const float*)d_in[10];
    const float* out_w    = (const float*)d_in[11];
    const float* norm_f_w = (const float*)d_in[12];
    float* out = (float*)d_out;

    cudaFuncSetAttribute(k_hgemm<128,2,4,4,4,4>,
                         cudaFuncAttributeMaxDynamicSharedMemorySize, SMEM128);
    cudaFuncSetAttribute(k_hgemm<64,4,2,2,4,4>,
                         cudaFuncAttributeMaxDynamicSharedMemorySize, SMEM64);

    float *hb, *xn, *z, *uc, *dbl, *delta;
    __half *ah, *al, *whi, *wli, *who, *wlo;
    cudaGetSymbolAddress((void**)&hb,    g_h);
    cudaGetSymbolAddress((void**)&xn,    g_xn);
    cudaGetSymbolAddress((void**)&z,     g_z);
    cudaGetSymbolAddress((void**)&uc,    g_uc);
    cudaGetSymbolAddress((void**)&dbl,   g_dbl);
    cudaGetSymbolAddress((void**)&delta, g_delta);
    cudaGetSymbolAddress((void**)&ah,    g_ah);
    cudaGetSymbolAddress((void**)&al,    g_al);
    cudaGetSymbolAddress((void**)&whi,   g_wh_in);
    cudaGetSymbolAddress((void**)&wli,   g_wl_in);
    cudaGetSymbolAddress((void**)&who,   g_wh_out);
    cudaGetSymbolAddress((void**)&wlo,   g_wl_out);

    const int nD   = MM*DD;
    const int nDIN = MM*DINN;

    // split all weights into fp16 hi/lo planes (once per launch)
    {
        int n4 = NLL*2*DINN*DD/4;
        k_split<<<(n4 + 255)/256, 256>>>(in_w, whi, wli, n4);
        n4 = NLL*DD*DINN/4;
        k_split<<<(n4 + 255)/256, 256>>>(out_w, who, wlo, n4);
    }

    // forward circular permute
    k_permute<<<(nD + 255)/256, 256>>>(x, vs, hb, 0);

    for (int i = 0; i < NLL; i++) {
        // RMSNorm -> fp16 hi/lo planes [MM][DD]
        k_rmsnorm_split<<<MM, 256>>>(hb, norm_w + (long)i*DD, ah, al);
        // in_proj: z[M, 2*DIN]
        {
            dim3 grid(2*DINN/128, MM/128);
            k_hgemm<128,2,4,4,4,4><<<grid, 256, SMEM128>>>(
                ah, al, DD, whi + (size_t)i*2*DINN*DD, wli + (size_t)i*2*DINN*DD,
                z, 2*DINN, DD, 0);
        }
        // causal depthwise conv + silu
        k_conv<<<(nDIN + 255)/256, 256>>>(z, conv_w + (long)i*DINN*DCC,
                                          conv_b + (long)i*DINN, uc);
        // x_proj: dbl[M, 72]
        launch_gemm_small(uc, DINN, xp_w + (long)i*DBLW*DINN, dbl, DBLW, MM, DBLW, DINN, 0);
        // dt_proj: delta[M, DIN]
        launch_gemm_small(dbl, DBLW, dt_w + (long)i*DINN*DTRR, delta, DINN, MM, DINN, DTRR, 0);
        // selective scan -> fp16 hi/lo planes [MM][DINN]
        k_scan<<<BB*(DINN/256), 256>>>(delta, dt_b + (long)i*DINN, uc, z, dbl,
                                       A_log + (long)i*DINN*DSS,
                                       D_skip + (long)i*DINN, ah, al);
        // out_proj, accumulate into residual
        {
            dim3 grid(DD/64, MM/128);
            k_hgemm<64,4,2,2,4,4><<<grid, 256, SMEM64>>>(
                ah, al, DINN, who + (size_t)i*DD*DINN, wlo + (size_t)i*DD*DINN,
                hb, DD, DINN, 1);
        }
    }

    // final RMSNorm + reverse permute
    k_rmsnorm<<<MM, 256>>>(hb, norm_f_w, xn);
    k_permute<<<(nD + 255)/256, 256>>>(xn, vs, out, 1);
}

// round 5
// speedup vs baseline: 3.4126x; 1.5234x over previous
#include <cuda_runtime.h>
#include <cuda_fp16.h>
#include <cstdint>
#include <math.h>

#define BB   64
#define VV   30
#define DD   640
#define DINN 1280
#define DSS  16
#define DTRR 40
#define DCC  4
#define NLL  4
#define MM   (BB*VV)          // 1920
#define DBLW (DTRR + 2*DSS)   // 72
#define XPN  80               // padded x_proj N (72 -> 80)
#define DTK  64               // padded dt_proj K (40 -> 64)
#define XSPL 8                // x_proj split-K factor

// ---------------- scratch (device globals; no runtime allocation) ----------
__device__ float g_h[MM*DD];
__device__ float g_xn[MM*DD];
__device__ float g_z[MM*2*DINN];
__device__ float g_uc[MM*DINN];
__device__ float g_dbl[MM*DBLW];
__device__ float g_delta[MM*DINN];
__device__ float g_xp_part[XSPL*MM*XPN];
// fp16 planes
__device__ __half g_ah[MM*DINN];
__device__ __half g_al[MM*DINN];
__device__ __half g_dth[MM*DTK];
__device__ __half g_dtl[MM*DTK];
__device__ __half g_wh_in[NLL*2*DINN*DD];
__device__ __half g_wl_in[NLL*2*DINN*DD];
__device__ __half g_wh_out[NLL*DD*DINN];
__device__ __half g_wl_out[NLL*DD*DINN];
__device__ __half g_xph[NLL*XPN*DINN];
__device__ __half g_xpl[NLL*XPN*DINN];
__device__ __half g_dtwh[NLL*DINN*DTK];
__device__ __half g_dtwl[NLL*DINN*DTK];

// ======================= low-level helpers ==================================
__device__ __forceinline__ uint32_t smem_u32(const void* p) {
    uint32_t a;
    asm("{ .reg .u64 t; cvta.to.shared.u64 t, %1; cvt.u32.u64 %0, t; }"
        : "=r"(a) : "l"(p));
    return a;
}
__device__ __forceinline__ void cp_async16(uint32_t dst, const void* src) {
    asm volatile("cp.async.cg.shared.global [%0], [%1], 16;" :: "r"(dst), "l"(src));
}
#define CP_COMMIT() asm volatile("cp.async.commit_group;" ::: "memory")
#define CP_WAIT(N)  asm volatile("cp.async.wait_group %0;" :: "n"(N) : "memory")
#define LDSM_X4(R, addr) \
    asm volatile("ldmatrix.sync.aligned.m8n8.x4.shared.b16 {%0,%1,%2,%3}, [%4];" \
        : "=r"((R)[0]), "=r"((R)[1]), "=r"((R)[2]), "=r"((R)[3]) : "r"(addr))

__device__ __forceinline__ void mma_f16(float* c, const uint32_t* a, const uint32_t* b) {
    asm volatile(
        "mma.sync.aligned.m16n8k16.row.col.f32.f16.f16.f32 "
        "{%0,%1,%2,%3}, {%4,%5,%6,%7}, {%8,%9}, {%0,%1,%2,%3};"
        : "+f"(c[0]), "+f"(c[1]), "+f"(c[2]), "+f"(c[3])
        : "r"(a[0]), "r"(a[1]), "r"(a[2]), "r"(a[3]), "r"(b[0]), "r"(b[1]));
}

// ======================= fp16 hi/lo 3-product HGEMM =========================
// C[M,N] (+)= A[M,K] * W[N,K]^T ; A,W as fp16 hi/lo planes; 128 x TN CTA tile.
// Optional split-K via blockIdx.z (klen per split, partStride output offset).
#define BKH    32
#define RP     40     // smem row stride in halves (80B), ldmatrix conflict-free

template<int TN, int WNW, int MAT, int NAT, int STAGES, int THREADS>
__global__ void __launch_bounds__(THREADS)
k_hgemm(const __half* __restrict__ Ah, const __half* __restrict__ Al, int lda,
        const __half* __restrict__ Wh, const __half* __restrict__ Wl, int ldw,
        float* __restrict__ C, int ldc, int klen, long partStride, int accumulate)
{
    extern __shared__ char sm[];
    constexpr int PLA   = 128 * RP * 2;
    constexpr int PLB   = TN  * RP * 2;
    constexpr int STAGE = 2*PLA + 2*PLB;

    const int tid = threadIdx.x, lane = tid & 31, wid = tid >> 5;
    const int wm = wid / WNW, wn = wid % WNW;
    const int m0 = blockIdx.y * 128, n0 = blockIdx.x * TN;
    const int kbase = blockIdx.z * klen;
    C += (long)blockIdx.z * partStride;
    const uint32_t sb = smem_u32(sm);

    const int g  = lane >> 3, lr = lane & 7;
    const int a_row = ((g & 1) ? 8 : 0) + lr;
    const int a_kg  = (g >> 1);
    const int b_row = ((g >> 1) ? 8 : 0) + lr;
    const int b_kg  = (g & 1);

    float acc[MAT][NAT][4];
#pragma unroll
    for (int i = 0; i < MAT; i++)
#pragma unroll
        for (int j = 0; j < NAT; j++)
#pragma unroll
            for (int q = 0; q < 4; q++) acc[i][j][q] = 0.f;

    const int nch = klen / BKH;

    auto load_stage = [&](int st, int ch) {
        const uint32_t sa = sb + st * STAGE;
        const int kb = kbase + ch * BKH;
#pragma unroll
        for (int c = tid; c < 512; c += THREADS) {
            int r = c >> 2, kg = c & 3;
            size_t go = (size_t)(m0 + r) * lda + kb + kg * 8;
            uint32_t so = (uint32_t)(r * (RP*2) + kg * 16);
            cp_async16(sa + so,        Ah + go);
            cp_async16(sa + PLA + so,  Al + go);
        }
#pragma unroll
        for (int c = tid; c < TN*4; c += THREADS) {
            int r = c >> 2, kg = c & 3;
            size_t go = (size_t)(n0 + r) * ldw + kb + kg * 8;
            uint32_t so = (uint32_t)(r * (RP*2) + kg * 16);
            cp_async16(sa + 2*PLA + so,        Wh + go);
            cp_async16(sa + 2*PLA + PLB + so,  Wl + go);
        }
        CP_COMMIT();
    };

#pragma unroll
    for (int s = 0; s < STAGES - 1; s++) load_stage(s, s);

    for (int ch = 0; ch < nch; ch++) {
        int pre = ch + STAGES - 1;
        if (pre < nch) load_stage(pre % STAGES, pre);
        else           CP_COMMIT();
        CP_WAIT(STAGES - 2);
        __syncthreads();

        const uint32_t sa = sb + (ch % STAGES) * STAGE;
#pragma unroll
        for (int ks = 0; ks < 2; ks++) {
            uint32_t ah[MAT][4], al[MAT][4], bh[NAT][2], bl[NAT][2];
#pragma unroll
            for (int am = 0; am < MAT; am++) {
                int row = wm * (MAT*16) + am*16 + a_row;
                uint32_t ad = sa + row * (RP*2) + (ks*2 + a_kg) * 16;
                LDSM_X4(ah[am], ad);
                LDSM_X4(al[am], ad + PLA);
            }
#pragma unroll
            for (int p = 0; p < NAT/2; p++) {
                int row = wn * (NAT*8) + p*16 + b_row;
                uint32_t ad = sa + 2*PLA + row * (RP*2) + (ks*2 + b_kg) * 16;
                uint32_t th[4], tl[4];
                LDSM_X4(th, ad);
                LDSM_X4(tl, ad + PLB);
                bh[2*p][0]=th[0]; bh[2*p][1]=th[1]; bh[2*p+1][0]=th[2]; bh[2*p+1][1]=th[3];
                bl[2*p][0]=tl[0]; bl[2*p][1]=tl[1]; bl[2*p+1][0]=tl[2]; bl[2*p+1][1]=tl[3];
            }
#pragma unroll
            for (int am = 0; am < MAT; am++)
#pragma unroll
                for (int bn = 0; bn < NAT; bn++) {
                    mma_f16(acc[am][bn], ah[am], bh[bn]);
                    mma_f16(acc[am][bn], al[am], bh[bn]);
                    mma_f16(acc[am][bn], ah[am], bl[bn]);
                }
        }
        __syncthreads();
    }

    const int lq = lane & 3, lr4 = lane >> 2;
#pragma unroll
    for (int am = 0; am < MAT; am++) {
        int row = m0 + wm*(MAT*16) + am*16 + lr4;
#pragma unroll
        for (int bn = 0; bn < NAT; bn++) {
            int col = n0 + wn*(NAT*8) + bn*8 + lq*2;
            float* p0 = &C[(size_t)row       * ldc + col];
            float* p1 = &C[(size_t)(row + 8) * ldc + col];
            if (accumulate) {
                float2 o0 = *reinterpret_cast<float2*>(p0);
                float2 o1 = *reinterpret_cast<float2*>(p1);
                o0.x += acc[am][bn][0]; o0.y += acc[am][bn][1];
                o1.x += acc[am][bn][2]; o1.y += acc[am][bn][3];
                *reinterpret_cast<float2*>(p0) = o0;
                *reinterpret_cast<float2*>(p1) = o1;
            } else {
                *reinterpret_cast<float2*>(p0) = make_float2(acc[am][bn][0], acc[am][bn][1]);
                *reinterpret_cast<float2*>(p1) = make_float2(acc[am][bn][2], acc[am][bn][3]);
            }
        }
    }
}

// ---------------- fp32 -> fp16 hi/lo split (dense, for big weights) ---------
__global__ void k_split(const float* __restrict__ in, __half* __restrict__ hi,
                        __half* __restrict__ lo, int n4)
{
    int i = blockIdx.x * blockDim.x + threadIdx.x;
    if (i >= n4) return;
    float4 v = reinterpret_cast<const float4*>(in)[i];
    __half h0 = __float2half_rn(v.x), h1 = __float2half_rn(v.y);
    __half h2 = __float2half_rn(v.z), h3 = __float2half_rn(v.w);
    __half l0 = __float2half_rn(v.x - __half2float(h0));
    __half l1 = __float2half_rn(v.y - __half2float(h1));
    __half l2 = __float2half_rn(v.z - __half2float(h2));
    __half l3 = __float2half_rn(v.w - __half2float(h3));
    reinterpret_cast<__half2*>(hi)[2*i  ] = __halves2half2(h0, h1);
    reinterpret_cast<__half2*>(hi)[2*i+1] = __halves2half2(h2, h3);
    reinterpret_cast<__half2*>(lo)[2*i  ] = __halves2half2(l0, l1);
    reinterpret_cast<__half2*>(lo)[2*i+1] = __halves2half2(l2, l3);
}

// ---------------- fp32 -> fp16 hi/lo split with zero padding ----------------
__global__ void k_split_pad(const float* __restrict__ in, __half* __restrict__ hi,
                            __half* __restrict__ lo, int R, int Cc, int PR, int PC, int L)
{
    int idx = blockIdx.x * blockDim.x + threadIdx.x;
    if (idx >= L*PR*PC) return;
    int c = idx % PC, r = (idx / PC) % PR, l = idx / (PC*PR);
    float v = (r < R && c < Cc) ? in[((long)l*R + r)*Cc + c] : 0.f;
    __half h = __float2half_rn(v);
    hi[idx] = h;
    lo[idx] = __float2half_rn(v - __half2float(h));
}

// ---------------- x_proj split-K reduce + dt-plane emit ---------------------
__global__ void k_xp_reduce(const float* __restrict__ part,
                            float* __restrict__ dbl,
                            __half* __restrict__ dth, __half* __restrict__ dtl)
{
    int idx = blockIdx.x * blockDim.x + threadIdx.x;
    if (idx >= MM*XPN) return;
    int j = idx % XPN, m = idx / XPN;
    float s = 0.f;
#pragma unroll
    for (int p = 0; p < XSPL; p++) s += part[(long)p*MM*XPN + idx];
    if (j < DBLW) dbl[(long)m*DBLW + j] = s;
    if (j < DTK) {
        float v = (j < DTRR) ? s : 0.f;
        __half h = __float2half_rn(v);
        dth[(long)m*DTK + j] = h;
        dtl[(long)m*DTK + j] = __float2half_rn(v - __half2float(h));
    }
}

// ---------------- permute ----------------------------------------------------
__global__ void k_permute(const float* __restrict__ in, const int* __restrict__ vs,
                          float* __restrict__ out, int rev)
{
    int idx = blockIdx.x * blockDim.x + threadIdx.x;
    if (idx >= MM*DD) return;
    int d = idx % DD;
    int m = idx / DD;
    int t = m % VV, b = m / VV;
    int v = vs[b];
    int src = rev ? ((t + v) % VV) : ((t + VV - v) % VV);
    out[idx] = in[(b*VV + src)*DD + d];
}

// ---------------- RMSNorm helpers --------------------------------------------
__device__ __forceinline__ float rms_scale(const float* row, int tid, int bdim)
{
    float ss = 0.f;
    for (int i = tid; i < DD; i += bdim) { float v = row[i]; ss += v*v; }
    __shared__ float red[32];
    for (int o = 16; o; o >>= 1) ss += __shfl_xor_sync(0xffffffffu, ss, o);
    if ((tid & 31) == 0) red[tid >> 5] = ss;
    __syncthreads();
    if (tid < 32) {
        float v = (tid < (bdim >> 5)) ? red[tid] : 0.f;
        for (int o = 16; o; o >>= 1) v += __shfl_xor_sync(0xffffffffu, v, o);
        red[tid] = v;
    }
    __syncthreads();
    return rsqrtf(red[0] * (1.f/DD) + 1e-5f);
}

__global__ void k_rmsnorm(const float* __restrict__ in, const float* __restrict__ w,
                          float* __restrict__ out)
{
    int m = blockIdx.x;
    const float* row = in + m*DD;
    float scale = rms_scale(row, threadIdx.x, blockDim.x);
    for (int i = threadIdx.x; i < DD; i += blockDim.x)
        out[m*DD + i] = row[i] * scale * w[i];
}

__global__ void k_rmsnorm_split(const float* __restrict__ in, const float* __restrict__ w,
                                __half* __restrict__ oh, __half* __restrict__ ol)
{
    int m = blockIdx.x;
    const float* row = in + m*DD;
    float scale = rms_scale(row, threadIdx.x, blockDim.x);
    for (int i = threadIdx.x; i < DD; i += blockDim.x) {
        float o = row[i] * scale * w[i];
        __half h = __float2half_rn(o);
        oh[m*DD + i] = h;
        ol[m*DD + i] = __float2half_rn(o - __half2float(h));
    }
}

// ---------------- causal depthwise conv + SiLU, emits fp32 + fp16 planes ----
__global__ void k_conv(const float* __restrict__ z, const float* __restrict__ cw,
                       const float* __restrict__ cb, float* __restrict__ uc,
                       __half* __restrict__ uch, __half* __restrict__ ucl)
{
    int idx = blockIdx.x * blockDim.x + threadIdx.x;
    if (idx >= MM*DINN) return;
    int d = idx % DINN;
    int m = idx / DINN;
    int t = m % VV, b = m / VV;
    float acc = cb[d];
#pragma unroll
    for (int h = 0; h < DCC; h++) {
        int tt = t + h - (DCC - 1);
        if (tt >= 0) acc += cw[d*DCC + h] * z[(long)(b*VV + tt)*(2*DINN) + d];
    }
    float u = acc / (1.f + __expf(-acc));
    uc[idx] = u;
    __half h2 = __float2half_rn(u);
    uch[idx] = h2;
    ucl[idx] = __float2half_rn(u - __half2float(h2));
}

// ---------------- selective scan (softplus + gate fused; fp16 plane out) ----
__global__ void k_scan(const float* __restrict__ delta_raw,
                       const float* __restrict__ dt_b,
                       const float* __restrict__ uc,
                       const float* __restrict__ z,
                       const float* __restrict__ dbl, const float* __restrict__ A_log,
                       const float* __restrict__ Dsk,
                       __half* __restrict__ yh, __half* __restrict__ yl)
{
    __shared__ float sB[VV][DSS];
    __shared__ float sC[VV][DSS];
    const int chunks = DINN / 256;
    int b  = blockIdx.x / chunks;
    int dc = blockIdx.x % chunks;
    int d  = dc * 256 + threadIdx.x;

    for (int i = threadIdx.x; i < VV*DSS; i += 256) {
        int t = i / DSS, s = i % DSS;
        const float* row = dbl + (long)(b*VV + t) * DBLW;
        sB[t][s] = row[DTRR + s];
        sC[t][s] = row[DTRR + DSS + s];
    }
    __syncthreads();

    float a[DSS], h[DSS];
#pragma unroll
    for (int s = 0; s < DSS; s++) {
        a[s] = -expf(A_log[(long)d*DSS + s]);
        h[s] = 0.f;
    }
    float dsk = Dsk[d];
    float bias = dt_b[d];

    for (int t = 0; t < VV; t++) {
        long m = (long)(b*VV + t);
        float dv = delta_raw[m*DINN + d] + bias;
        float dl = fmaxf(dv, 0.f) + log1pf(__expf(-fabsf(dv)));
        float uu = uc[m*DINN + d];
        float du = dl * uu;
        float acc = 0.f;
#pragma unroll
        for (int s = 0; s < DSS; s++) {
            float dA = __expf(dl * a[s]);
            h[s] = dA * h[s] + du * sB[t][s];
            acc += h[s] * sC[t][s];
        }
        float r = z[m*(2*DINN) + DINN + d];
        float yv = (acc + uu * dsk) * (r / (1.f + __expf(-r)));
        __half hh = __float2half_rn(yv);
        yh[m*DINN + d] = hh;
        yl[m*DINN + d] = __float2half_rn(yv - __half2float(hh));
    }
}

// ---------------- host orchestration ----------------------------------------
#define ST_IN  (2*(128*RP*2) + 2*(256*RP*2))   // 61440
#define ST_OUT (2*(128*RP*2) + 2*(64*RP*2))    // 30720
#define ST_XP  (2*(128*RP*2) + 2*(XPN*RP*2))   // 33280
#define ST_DT  (2*(128*RP*2) + 2*(128*RP*2))   // 40960
#define SMEM_IN  (3*ST_IN)    // 184320
#define SMEM_OUT (4*ST_OUT)   // 122880
#define SMEM_XP  (3*ST_XP)    // 99840
#define SMEM_DT  (2*ST_DT)    // 81920

extern "C" void kernel_launch(void* const* d_in, const int* in_sizes, int n_in,
                              void* d_out, int out_size)
{
    const float* x        = (const float*)d_in[0];
    const int*   vs       = (const int*)  d_in[1];
    const float* norm_w   = (const float*)d_in[2];
    const float* in_w     = (const float*)d_in[3];
    const float* conv_w   = (const float*)d_in[4];
    const float* conv_b   = (const float*)d_in[5];
    const float* xp_w     = (const float*)d_in[6];
    const float* dt_w     = (const float*)d_in[7];
    const float* dt_b     = (const float*)d_in[8];
    const float* A_log    = (const float*)d_in[9];
    const float* D_skip   = (const float*)d_in[10];
    const float* out_w    = (const float*)d_in[11];
    const float* norm_f_w = (const float*)d_in[12];
    float* out = (float*)d_out;

    cudaFuncSetAttribute((void*)k_hgemm<256,8,4,4,3,512>,
                         cudaFuncAttributeMaxDynamicSharedMemorySize, SMEM_IN);
    cudaFuncSetAttribute((void*)k_hgemm<64,2,2,4,4,256>,
                         cudaFuncAttributeMaxDynamicSharedMemorySize, SMEM_OUT);
    cudaFuncSetAttribute((void*)k_hgemm<XPN,1,1,10,3,256>,
                         cudaFuncAttributeMaxDynamicSharedMemorySize, SMEM_XP);
    cudaFuncSetAttribute((void*)k_hgemm<128,4,4,4,2,256>,
                         cudaFuncAttributeMaxDynamicSharedMemorySize, SMEM_DT);

    float *hb, *xn, *z, *uc, *dbl, *delta, *xpp;
    __half *ah, *al, *dth, *dtl, *whi, *wli, *who, *wlo, *xph, *xpl, *dtwh, *dtwl;
    cudaGetSymbolAddress((void**)&hb,    g_h);
    cudaGetSymbolAddress((void**)&xn,    g_xn);
    cudaGetSymbolAddress((void**)&z,     g_z);
    cudaGetSymbolAddress((void**)&uc,    g_uc);
    cudaGetSymbolAddress((void**)&dbl,   g_dbl);
    cudaGetSymbolAddress((void**)&delta, g_delta);
    cudaGetSymbolAddress((void**)&xpp,   g_xp_part);
    cudaGetSymbolAddress((void**)&ah,    g_ah);
    cudaGetSymbolAddress((void**)&al,    g_al);
    cudaGetSymbolAddress((void**)&dth,   g_dth);
    cudaGetSymbolAddress((void**)&dtl,   g_dtl);
    cudaGetSymbolAddress((void**)&whi,   g_wh_in);
    cudaGetSymbolAddress((void**)&wli,   g_wl_in);
    cudaGetSymbolAddress((void**)&who,   g_wh_out);
    cudaGetSymbolAddress((void**)&wlo,   g_wl_out);
    cudaGetSymbolAddress((void**)&xph,   g_xph);
    cudaGetSymbolAddress((void**)&xpl,   g_xpl);
    cudaGetSymbolAddress((void**)&dtwh,  g_dtwh);
    cudaGetSymbolAddress((void**)&dtwl,  g_dtwl);

    const int nD   = MM*DD;
    const int nDIN = MM*DINN;

    // weight plane prep (once per launch)
    {
        int n4 = NLL*2*DINN*DD/4;
        k_split<<<(n4 + 255)/256, 256>>>(in_w, whi, wli, n4);
        n4 = NLL*DD*DINN/4;
        k_split<<<(n4 + 255)/256, 256>>>(out_w, who, wlo, n4);
        int n = NLL*XPN*DINN;
        k_split_pad<<<(n + 255)/256, 256>>>(xp_w, xph, xpl, DBLW, DINN, XPN, DINN, NLL);
        n = NLL*DINN*DTK;
        k_split_pad<<<(n + 255)/256, 256>>>(dt_w, dtwh, dtwl, DINN, DTRR, DINN, DTK, NLL);
    }

    k_permute<<<(nD + 255)/256, 256>>>(x, vs, hb, 0);

    for (int i = 0; i < NLL; i++) {
        // RMSNorm -> fp16 planes
        k_rmsnorm_split<<<MM, 256>>>(hb, norm_w + (long)i*DD, ah, al);
        // in_proj (one wave: 150 CTAs of 128x256)
        {
            dim3 grid(2*DINN/256, MM/128);
            k_hgemm<256,8,4,4,3,512><<<grid, 512, SMEM_IN>>>(
                ah, al, DD, whi + (size_t)i*2*DINN*DD, wli + (size_t)i*2*DINN*DD, DD,
                z, 2*DINN, DD, 0, 0);
        }
        // conv + silu -> uc fp32 + fp16 planes (into ah/al, reused)
        k_conv<<<(nDIN + 255)/256, 256>>>(z, conv_w + (long)i*DINN*DCC,
                                          conv_b + (long)i*DINN, uc, ah, al);
        // x_proj split-K (8 x 160) into partials, then reduce -> dbl + dt planes
        {
            dim3 grid(1, MM/128, XSPL);
            k_hgemm<XPN,1,1,10,3,256><<<grid, 256, SMEM_XP>>>(
                ah, al, DINN, xph + (size_t)i*XPN*DINN, xpl + (size_t)i*XPN*DINN, DINN,
                xpp, XPN, DINN/XSPL, (long)MM*XPN, 0);
            int n = MM*XPN;
            k_xp_reduce<<<(n + 255)/256, 256>>>(xpp, dbl, dth, dtl);
        }
        // dt_proj (K padded to 64)
        {
            dim3 grid(DINN/128, MM/128);
            k_hgemm<128,4,4,4,2,256><<<grid, 256, SMEM_DT>>>(
                dth, dtl, DTK, dtwh + (size_t)i*DINN*DTK, dtwl + (size_t)i*DINN*DTK, DTK,
                delta, DINN, DTK, 0, 0);
        }
        // selective scan -> y fp16 planes (ah/al reused again)
        k_scan<<<BB*(DINN/256), 256>>>(delta, dt_b + (long)i*DINN, uc, z, dbl,
                                       A_log + (long)i*DINN*DSS,
                                       D_skip + (long)i*DINN, ah, al);
        // out_proj accumulate into residual
        {
            dim3 grid(DD/64, MM/128);
            k_hgemm<64,2,2,4,4,256><<<grid, 256, SMEM_OUT>>>(
                ah, al, DINN, who + (size_t)i*DD*DINN, wlo + (size_t)i*DD*DINN, DINN,
                hb, DD, DINN, 0, 1);
        }
    }

    k_rmsnorm<<<MM, 256>>>(hb, norm_f_w, xn);
    k_permute<<<(nD + 255)/256, 256>>>(xn, vs, out, 1);
}

// round 6
// speedup vs baseline: 3.8617x; 1.1316x over previous
#include <cuda_runtime.h>
#include <cuda_fp16.h>
#include <cstdint>
#include <math.h>

#define BB   64
#define VV   30
#define DD   640
#define DINN 1280
#define DSS  16
#define DTRR 40
#define DCC  4
#define NLL  4
#define MM   (BB*VV)          // 1920
#define DBLW (DTRR + 2*DSS)   // 72
#define XPN  80               // padded x_proj N (72 -> 80)
#define DTK  64               // padded dt_proj K (40 -> 64)
#define XSPL 8                // x_proj split-K factor

// ---------------- scratch (device globals; no runtime allocation) ----------
__device__ float g_h[MM*DD];
__device__ float g_z[MM*2*DINN];
__device__ float g_uc[MM*DINN];
__device__ float g_dbl[MM*DBLW];
__device__ float g_delta[MM*DINN];
__device__ float g_xp_part[XSPL*MM*XPN];
// fp16 planes
__device__ __half g_ah[MM*DINN];
__device__ __half g_al[MM*DINN];
__device__ __half g_dth[MM*DTK];
__device__ __half g_dtl[MM*DTK];
__device__ __half g_wh_in[NLL*2*DINN*DD];     // hi only (2-product)
__device__ __half g_wh_out[NLL*DD*DINN];
__device__ __half g_wl_out[NLL*DD*DINN];      // out_proj keeps 3-product
__device__ __half g_xph[NLL*XPN*DINN];        // hi only
__device__ __half g_dtwh[NLL*DINN*DTK];       // hi only

// ======================= low-level helpers ==================================
__device__ __forceinline__ uint32_t smem_u32(const void* p) {
    uint32_t a;
    asm("{ .reg .u64 t; cvta.to.shared.u64 t, %1; cvt.u32.u64 %0, t; }"
        : "=r"(a) : "l"(p));
    return a;
}
__device__ __forceinline__ void cp_async16(uint32_t dst, const void* src) {
    asm volatile("cp.async.cg.shared.global [%0], [%1], 16;" :: "r"(dst), "l"(src));
}
#define CP_COMMIT() asm volatile("cp.async.commit_group;" ::: "memory")
#define CP_WAIT(N)  asm volatile("cp.async.wait_group %0;" :: "n"(N) : "memory")
#define LDSM_X4(R, addr) \
    asm volatile("ldmatrix.sync.aligned.m8n8.x4.shared.b16 {%0,%1,%2,%3}, [%4];" \
        : "=r"((R)[0]), "=r"((R)[1]), "=r"((R)[2]), "=r"((R)[3]) : "r"(addr))

__device__ __forceinline__ void mma_f16(float* c, const uint32_t* a, const uint32_t* b) {
    asm volatile(
        "mma.sync.aligned.m16n8k16.row.col.f32.f16.f16.f32 "
        "{%0,%1,%2,%3}, {%4,%5,%6,%7}, {%8,%9}, {%0,%1,%2,%3};"
        : "+f"(c[0]), "+f"(c[1]), "+f"(c[2]), "+f"(c[3])
        : "r"(a[0]), "r"(a[1]), "r"(a[2]), "r"(a[3]), "r"(b[0]), "r"(b[1]));
}

// ======================= fp16 hi/lo HGEMM (2- or 3-product) =================
// C[M,N] (+)= A[M,K] * W[N,K]^T. A always hi/lo; W hi (+lo iff PROD==3).
// PROD==2: acc = (ah+al)*wh  (drops a*wl, |wl|<=2^-12|w|)
// PROD==3: acc = ah*wh + al*wh + ah*wl
#define BKH    32
#define RP     40     // smem row stride in halves (80B), ldmatrix conflict-free

template<int TN, int WNW, int MAT, int NAT, int STAGES, int THREADS, int PROD>
__global__ void __launch_bounds__(THREADS)
k_hgemm(const __half* __restrict__ Ah, const __half* __restrict__ Al, int lda,
        const __half* __restrict__ Wh, const __half* __restrict__ Wl, int ldw,
        float* __restrict__ C, int ldc, int klen, long partStride, int accumulate)
{
    extern __shared__ char sm[];
    constexpr int PLA   = 128 * RP * 2;
    constexpr int PLB   = TN  * RP * 2;
    constexpr int WPL   = (PROD == 3) ? 2 : 1;
    constexpr int STAGE = 2*PLA + WPL*PLB;

    const int tid = threadIdx.x, lane = tid & 31, wid = tid >> 5;
    const int wm = wid / WNW, wn = wid % WNW;
    const int m0 = blockIdx.y * 128, n0 = blockIdx.x * TN;
    const int kbase = blockIdx.z * klen;
    C += (long)blockIdx.z * partStride;
    const uint32_t sb = smem_u32(sm);

    const int g  = lane >> 3, lr = lane & 7;
    const int a_row = ((g & 1) ? 8 : 0) + lr;
    const int a_kg  = (g >> 1);
    const int b_row = ((g >> 1) ? 8 : 0) + lr;
    const int b_kg  = (g & 1);

    float acc[MAT][NAT][4];
#pragma unroll
    for (int i = 0; i < MAT; i++)
#pragma unroll
        for (int j = 0; j < NAT; j++)
#pragma unroll
            for (int q = 0; q < 4; q++) acc[i][j][q] = 0.f;

    const int nch = klen / BKH;

    auto load_stage = [&](int st, int ch) {
        const uint32_t sa = sb + st * STAGE;
        const int kb = kbase + ch * BKH;
#pragma unroll
        for (int c = tid; c < 512; c += THREADS) {
            int r = c >> 2, kg = c & 3;
            size_t go = (size_t)(m0 + r) * lda + kb + kg * 8;
            uint32_t so = (uint32_t)(r * (RP*2) + kg * 16);
            cp_async16(sa + so,        Ah + go);
            cp_async16(sa + PLA + so,  Al + go);
        }
#pragma unroll
        for (int c = tid; c < TN*4; c += THREADS) {
            int r = c >> 2, kg = c & 3;
            size_t go = (size_t)(n0 + r) * ldw + kb + kg * 8;
            uint32_t so = (uint32_t)(r * (RP*2) + kg * 16);
            cp_async16(sa + 2*PLA + so, Wh + go);
            if (PROD == 3) cp_async16(sa + 2*PLA + PLB + so, Wl + go);
        }
        CP_COMMIT();
    };

#pragma unroll
    for (int s = 0; s < STAGES - 1; s++) load_stage(s, s);

    for (int ch = 0; ch < nch; ch++) {
        int pre = ch + STAGES - 1;
        if (pre < nch) load_stage(pre % STAGES, pre);
        else           CP_COMMIT();
        CP_WAIT(STAGES - 2);
        __syncthreads();

        const uint32_t sa = sb + (ch % STAGES) * STAGE;
#pragma unroll
        for (int ks = 0; ks < 2; ks++) {
            uint32_t ah[MAT][4], al[MAT][4], bh[NAT][2], bl[NAT][2];
#pragma unroll
            for (int am = 0; am < MAT; am++) {
                int row = wm * (MAT*16) + am*16 + a_row;
                uint32_t ad = sa + row * (RP*2) + (ks*2 + a_kg) * 16;
                LDSM_X4(ah[am], ad);
                LDSM_X4(al[am], ad + PLA);
            }
#pragma unroll
            for (int p = 0; p < NAT/2; p++) {
                int row = wn * (NAT*8) + p*16 + b_row;
                uint32_t ad = sa + 2*PLA + row * (RP*2) + (ks*2 + b_kg) * 16;
                uint32_t th[4];
                LDSM_X4(th, ad);
                bh[2*p][0]=th[0]; bh[2*p][1]=th[1]; bh[2*p+1][0]=th[2]; bh[2*p+1][1]=th[3];
                if (PROD == 3) {
                    uint32_t tl[4];
                    LDSM_X4(tl, ad + PLB);
                    bl[2*p][0]=tl[0]; bl[2*p][1]=tl[1]; bl[2*p+1][0]=tl[2]; bl[2*p+1][1]=tl[3];
                }
            }
#pragma unroll
            for (int am = 0; am < MAT; am++)
#pragma unroll
                for (int bn = 0; bn < NAT; bn++) {
                    mma_f16(acc[am][bn], ah[am], bh[bn]);
                    mma_f16(acc[am][bn], al[am], bh[bn]);
                    if (PROD == 3) mma_f16(acc[am][bn], ah[am], bl[bn]);
                }
        }
        __syncthreads();
    }

    const int lq = lane & 3, lr4 = lane >> 2;
#pragma unroll
    for (int am = 0; am < MAT; am++) {
        int row = m0 + wm*(MAT*16) + am*16 + lr4;
#pragma unroll
        for (int bn = 0; bn < NAT; bn++) {
            int col = n0 + wn*(NAT*8) + bn*8 + lq*2;
            float* p0 = &C[(size_t)row       * ldc + col];
            float* p1 = &C[(size_t)(row + 8) * ldc + col];
            if (accumulate) {
                float2 o0 = *reinterpret_cast<float2*>(p0);
                float2 o1 = *reinterpret_cast<float2*>(p1);
                o0.x += acc[am][bn][0]; o0.y += acc[am][bn][1];
                o1.x += acc[am][bn][2]; o1.y += acc[am][bn][3];
                *reinterpret_cast<float2*>(p0) = o0;
                *reinterpret_cast<float2*>(p1) = o1;
            } else {
                *reinterpret_cast<float2*>(p0) = make_float2(acc[am][bn][0], acc[am][bn][1]);
                *reinterpret_cast<float2*>(p1) = make_float2(acc[am][bn][2], acc[am][bn][3]);
            }
        }
    }
}

// ---------------- weight conversion kernels ---------------------------------
__global__ void k_split(const float* __restrict__ in, __half* __restrict__ hi,
                        __half* __restrict__ lo, int n4)
{
    int i = blockIdx.x * blockDim.x + threadIdx.x;
    if (i >= n4) return;
    float4 v = reinterpret_cast<const float4*>(in)[i];
    __half h0 = __float2half_rn(v.x), h1 = __float2half_rn(v.y);
    __half h2 = __float2half_rn(v.z), h3 = __float2half_rn(v.w);
    __half l0 = __float2half_rn(v.x - __half2float(h0));
    __half l1 = __float2half_rn(v.y - __half2float(h1));
    __half l2 = __float2half_rn(v.z - __half2float(h2));
    __half l3 = __float2half_rn(v.w - __half2float(h3));
    reinterpret_cast<__half2*>(hi)[2*i  ] = __halves2half2(h0, h1);
    reinterpret_cast<__half2*>(hi)[2*i+1] = __halves2half2(h2, h3);
    reinterpret_cast<__half2*>(lo)[2*i  ] = __halves2half2(l0, l1);
    reinterpret_cast<__half2*>(lo)[2*i+1] = __halves2half2(l2, l3);
}

__global__ void k_split_hi(const float* __restrict__ in, __half* __restrict__ hi, int n4)
{
    int i = blockIdx.x * blockDim.x + threadIdx.x;
    if (i >= n4) return;
    float4 v = reinterpret_cast<const float4*>(in)[i];
    reinterpret_cast<__half2*>(hi)[2*i  ] =
        __halves2half2(__float2half_rn(v.x), __float2half_rn(v.y));
    reinterpret_cast<__half2*>(hi)[2*i+1] =
        __halves2half2(__float2half_rn(v.z), __float2half_rn(v.w));
}

__global__ void k_split_pad_hi(const float* __restrict__ in, __half* __restrict__ hi,
                               int R, int Cc, int PR, int PC, int L)
{
    int idx = blockIdx.x * blockDim.x + threadIdx.x;
    if (idx >= L*PR*PC) return;
    int c = idx % PC, r = (idx / PC) % PR, l = idx / (PC*PR);
    float v = (r < R && c < Cc) ? in[((long)l*R + r)*Cc + c] : 0.f;
    hi[idx] = __float2half_rn(v);
}

// ---------------- x_proj split-K reduce + dt-plane emit ---------------------
__global__ void k_xp_reduce(const float* __restrict__ part,
                            float* __restrict__ dbl,
                            __half* __restrict__ dth, __half* __restrict__ dtl)
{
    int idx = blockIdx.x * blockDim.x + threadIdx.x;
    if (idx >= MM*XPN) return;
    int j = idx % XPN, m = idx / XPN;
    float s = 0.f;
#pragma unroll
    for (int p = 0; p < XSPL; p++) s += part[(long)p*MM*XPN + idx];
    if (j < DBLW) dbl[(long)m*DBLW + j] = s;
    if (j < DTK) {
        float v = (j < DTRR) ? s : 0.f;
        __half h = __float2half_rn(v);
        dth[(long)m*DTK + j] = h;
        dtl[(long)m*DTK + j] = __float2half_rn(v - __half2float(h));
    }
}

// ---------------- permute ----------------------------------------------------
__global__ void k_permute(const float* __restrict__ in, const int* __restrict__ vs,
                          float* __restrict__ out)
{
    int idx = blockIdx.x * blockDim.x + threadIdx.x;
    if (idx >= MM*DD) return;
    int d = idx % DD;
    int m = idx / DD;
    int t = m % VV, b = m / VV;
    int v = vs[b];
    int src = (t + VV - v) % VV;
    out[idx] = in[(b*VV + src)*DD + d];
}

// ---------------- RMSNorm helpers --------------------------------------------
__device__ __forceinline__ float rms_scale(const float* row, int tid, int bdim)
{
    float ss = 0.f;
    for (int i = tid; i < DD; i += bdim) { float v = row[i]; ss += v*v; }
    __shared__ float red[32];
    for (int o = 16; o; o >>= 1) ss += __shfl_xor_sync(0xffffffffu, ss, o);
    if ((tid & 31) == 0) red[tid >> 5] = ss;
    __syncthreads();
    if (tid < 32) {
        float v = (tid < (bdim >> 5)) ? red[tid] : 0.f;
        for (int o = 16; o; o >>= 1) v += __shfl_xor_sync(0xffffffffu, v, o);
        red[tid] = v;
    }
    __syncthreads();
    return rsqrtf(red[0] * (1.f/DD) + 1e-5f);
}

__global__ void k_rmsnorm_split(const float* __restrict__ in, const float* __restrict__ w,
                                __half* __restrict__ oh, __half* __restrict__ ol)
{
    int m = blockIdx.x;
    const float* row = in + m*DD;
    float scale = rms_scale(row, threadIdx.x, blockDim.x);
    for (int i = threadIdx.x; i < DD; i += blockDim.x) {
        float o = row[i] * scale * w[i];
        __half h = __float2half_rn(o);
        oh[m*DD + i] = h;
        ol[m*DD + i] = __float2half_rn(o - __half2float(h));
    }
}

// final RMSNorm fused with reverse circular permute
__global__ void k_rmsnorm_perm(const float* __restrict__ in, const float* __restrict__ w,
                               const int* __restrict__ vs, float* __restrict__ out)
{
    int m = blockIdx.x;
    int t = m % VV, b = m / VV;
    const float* row = in + m*DD;
    float scale = rms_scale(row, threadIdx.x, blockDim.x);
    int v = vs[b];
    int tdst = (t - v + VV) % VV;      // out[:, tdst] = h[:, (tdst+v)%V] = h[:, t]
    float* orow = out + (long)(b*VV + tdst)*DD;
    for (int i = threadIdx.x; i < DD; i += blockDim.x)
        orow[i] = row[i] * scale * w[i];
}

// ---------------- causal depthwise conv + SiLU, emits fp32 + fp16 planes ----
__global__ void k_conv(const float* __restrict__ z, const float* __restrict__ cw,
                       const float* __restrict__ cb, float* __restrict__ uc,
                       __half* __restrict__ uch, __half* __restrict__ ucl)
{
    int idx = blockIdx.x * blockDim.x + threadIdx.x;
    if (idx >= MM*DINN) return;
    int d = idx % DINN;
    int m = idx / DINN;
    int t = m % VV, b = m / VV;
    float acc = cb[d];
#pragma unroll
    for (int h = 0; h < DCC; h++) {
        int tt = t + h - (DCC - 1);
        if (tt >= 0) acc += cw[d*DCC + h] * z[(long)(b*VV + tt)*(2*DINN) + d];
    }
    float u = acc / (1.f + __expf(-acc));
    uc[idx] = u;
    __half h2 = __float2half_rn(u);
    uch[idx] = h2;
    ucl[idx] = __float2half_rn(u - __half2float(h2));
}

// ---------------- selective scan (softplus + gate fused; fp16 plane out) ----
__global__ void k_scan(const float* __restrict__ delta_raw,
                       const float* __restrict__ dt_b,
                       const float* __restrict__ uc,
                       const float* __restrict__ z,
                       const float* __restrict__ dbl, const float* __restrict__ A_log,
                       const float* __restrict__ Dsk,
                       __half* __restrict__ yh, __half* __restrict__ yl)
{
    __shared__ float sB[VV][DSS];
    __shared__ float sC[VV][DSS];
    const int chunks = DINN / 256;
    int b  = blockIdx.x / chunks;
    int dc = blockIdx.x % chunks;
    int d  = dc * 256 + threadIdx.x;

    for (int i = threadIdx.x; i < VV*DSS; i += 256) {
        int t = i / DSS, s = i % DSS;
        const float* row = dbl + (long)(b*VV + t) * DBLW;
        sB[t][s] = row[DTRR + s];
        sC[t][s] = row[DTRR + DSS + s];
    }
    __syncthreads();

    float a[DSS], h[DSS];
#pragma unroll
    for (int s = 0; s < DSS; s++) {
        a[s] = -expf(A_log[(long)d*DSS + s]);
        h[s] = 0.f;
    }
    float dsk = Dsk[d];
    float bias = dt_b[d];

    for (int t = 0; t < VV; t++) {
        long m = (long)(b*VV + t);
        float dv = delta_raw[m*DINN + d] + bias;
        float dl = fmaxf(dv, 0.f) + log1pf(__expf(-fabsf(dv)));
        float uu = uc[m*DINN + d];
        float du = dl * uu;
        float acc = 0.f;
#pragma unroll
        for (int s = 0; s < DSS; s++) {
            float dA = __expf(dl * a[s]);
            h[s] = dA * h[s] + du * sB[t][s];
            acc += h[s] * sC[t][s];
        }
        float r = z[m*(2*DINN) + DINN + d];
        float yv = (acc + uu * dsk) * (r / (1.f + __expf(-r)));
        __half hh = __float2half_rn(yv);
        yh[m*DINN + d] = hh;
        yl[m*DINN + d] = __float2half_rn(yv - __half2float(hh));
    }
}

// ---------------- host orchestration ----------------------------------------
#define PLA_B   (128*RP*2)
#define ST_IN   (2*PLA_B + 256*RP*2)             // 2-product, TN=256: 40960
#define ST_OUT  (2*PLA_B + 2*(64*RP*2))          // 3-product, TN=64 : 30720
#define ST_XP   (2*PLA_B + XPN*RP*2)             // 2-product, TN=80 : 26880
#define ST_DT   (2*PLA_B + 128*RP*2)             // 2-product, TN=128: 30720
#define SMEM_IN  (4*ST_IN)    // 163840
#define SMEM_OUT (4*ST_OUT)   // 122880
#define SMEM_XP  (3*ST_XP)    // 80640
#define SMEM_DT  (2*ST_DT)    // 61440

extern "C" void kernel_launch(void* const* d_in, const int* in_sizes, int n_in,
                              void* d_out, int out_size)
{
    const float* x        = (const float*)d_in[0];
    const int*   vs       = (const int*)  d_in[1];
    const float* norm_w   = (const float*)d_in[2];
    const float* in_w     = (const float*)d_in[3];
    const float* conv_w   = (const float*)d_in[4];
    const float* conv_b   = (const float*)d_in[5];
    const float* xp_w     = (const float*)d_in[6];
    const float* dt_w     = (const float*)d_in[7];
    const float* dt_b     = (const float*)d_in[8];
    const float* A_log    = (const float*)d_in[9];
    const float* D_skip   = (const float*)d_in[10];
    const float* out_w    = (const float*)d_in[11];
    const float* norm_f_w = (const float*)d_in[12];
    float* out = (float*)d_out;

    cudaFuncSetAttribute((void*)k_hgemm<256,8,4,4,4,512,2>,
                         cudaFuncAttributeMaxDynamicSharedMemorySize, SMEM_IN);
    cudaFuncSetAttribute((void*)k_hgemm<64,2,2,4,4,256,3>,
                         cudaFuncAttributeMaxDynamicSharedMemorySize, SMEM_OUT);
    cudaFuncSetAttribute((void*)k_hgemm<XPN,1,1,10,3,256,2>,
                         cudaFuncAttributeMaxDynamicSharedMemorySize, SMEM_XP);
    cudaFuncSetAttribute((void*)k_hgemm<128,4,4,4,2,256,2>,
                         cudaFuncAttributeMaxDynamicSharedMemorySize, SMEM_DT);

    float *hb, *z, *uc, *dbl, *delta, *xpp;
    __half *ah, *al, *dth, *dtl, *whi, *who, *wlo, *xph, *dtwh;
    cudaGetSymbolAddress((void**)&hb,    g_h);
    cudaGetSymbolAddress((void**)&z,     g_z);
    cudaGetSymbolAddress((void**)&uc,    g_uc);
    cudaGetSymbolAddress((void**)&dbl,   g_dbl);
    cudaGetSymbolAddress((void**)&delta, g_delta);
    cudaGetSymbolAddress((void**)&xpp,   g_xp_part);
    cudaGetSymbolAddress((void**)&ah,    g_ah);
    cudaGetSymbolAddress((void**)&al,    g_al);
    cudaGetSymbolAddress((void**)&dth,   g_dth);
    cudaGetSymbolAddress((void**)&dtl,   g_dtl);
    cudaGetSymbolAddress((void**)&whi,   g_wh_in);
    cudaGetSymbolAddress((void**)&who,   g_wh_out);
    cudaGetSymbolAddress((void**)&wlo,   g_wl_out);
    cudaGetSymbolAddress((void**)&xph,   g_xph);
    cudaGetSymbolAddress((void**)&dtwh,  g_dtwh);

    const int nD   = MM*DD;
    const int nDIN = MM*DINN;

    // weight plane prep (once per launch; deterministic)
    {
        int n4 = NLL*2*DINN*DD/4;
        k_split_hi<<<(n4 + 255)/256, 256>>>(in_w, whi, n4);
        n4 = NLL*DD*DINN/4;
        k_split<<<(n4 + 255)/256, 256>>>(out_w, who, wlo, n4);
        int n = NLL*XPN*DINN;
        k_split_pad_hi<<<(n + 255)/256, 256>>>(xp_w, xph, DBLW, DINN, XPN, DINN, NLL);
        n = NLL*DINN*DTK;
        k_split_pad_hi<<<(n + 255)/256, 256>>>(dt_w, dtwh, DINN, DTRR, DINN, DTK, NLL);
    }

    k_permute<<<(nD + 255)/256, 256>>>(x, vs, hb);

    for (int i = 0; i < NLL; i++) {
        k_rmsnorm_split<<<MM, 256>>>(hb, norm_w + (long)i*DD, ah, al);
        // in_proj (2-product, one wave: 150 CTAs of 128x256)
        {
            dim3 grid(2*DINN/256, MM/128);
            k_hgemm<256,8,4,4,4,512,2><<<grid, 512, SMEM_IN>>>(
                ah, al, DD, whi + (size_t)i*2*DINN*DD, (const __half*)0, DD,
                z, 2*DINN, DD, 0, 0);
        }
        k_conv<<<(nDIN + 255)/256, 256>>>(z, conv_w + (long)i*DINN*DCC,
                                          conv_b + (long)i*DINN, uc, ah, al);
        // x_proj split-K (2-product)
        {
            dim3 grid(1, MM/128, XSPL);
            k_hgemm<XPN,1,1,10,3,256,2><<<grid, 256, SMEM_XP>>>(
                ah, al, DINN, xph + (size_t)i*XPN*DINN, (const __half*)0, DINN,
                xpp, XPN, DINN/XSPL, (long)MM*XPN, 0);
            int n = MM*XPN;
            k_xp_reduce<<<(n + 255)/256, 256>>>(xpp, dbl, dth, dtl);
        }
        // dt_proj (2-product, K padded to 64)
        {
            dim3 grid(DINN/128, MM/128);
            k_hgemm<128,4,4,4,2,256,2><<<grid, 256, SMEM_DT>>>(
                dth, dtl, DTK, dtwh + (size_t)i*DINN*DTK, (const __half*)0, DTK,
                delta, DINN, DTK, 0, 0);
        }
        k_scan<<<BB*(DINN/256), 256>>>(delta, dt_b + (long)i*DINN, uc, z, dbl,
                                       A_log + (long)i*DINN*DSS,
                                       D_skip + (long)i*DINN, ah, al);
        // out_proj (3-product, accumulate into residual)
        {
            dim3 grid(DD/64, MM/128);
            k_hgemm<64,2,2,4,4,256,3><<<grid, 256, SMEM_OUT>>>(
                ah, al, DINN, who + (size_t)i*DD*DINN, wlo + (size_t)i*DD*DINN, DINN,
                hb, DD, DINN, 0, 1);
        }
    }

    // final RMSNorm fused with reverse permute
    k_rmsnorm_perm<<<MM, 256>>>(hb, norm_f_w, vs, out);
}

// round 7
// speedup vs baseline: 4.9941x; 1.2932x over previous
#include <cuda_runtime.h>
#include <cuda_fp16.h>
#include <cstdint>
#include <math.h>

#define BB   64
#define VV   30
#define DD   640
#define DINN 1280
#define DSS  16
#define DTRR 40
#define DCC  4
#define NLL  4
#define MM   (BB*VV)          // 1920
#define DBLW (DTRR + 2*DSS)   // 72
#define XPN  80               // padded x_proj N (72 -> 80)
#define DTK  64               // padded dt_proj K (40 -> 64)
#define XSPL 8                // x_proj split-K factor

// ---------------- scratch (device globals; no runtime allocation) ----------
__device__ float g_h[MM*DD];
__device__ float g_z[MM*2*DINN];
__device__ float g_uc[MM*DINN];
__device__ float g_dbl[MM*DBLW];
__device__ float g_delta[MM*DINN];
__device__ float g_xp_part[XSPL*MM*XPN];
// fp16 planes (hi only — 1-product GEMMs)
__device__ __half g_ah[MM*DINN];
__device__ __half g_dth[MM*DTK];
__device__ __half g_wh_in[NLL*2*DINN*DD];
__device__ __half g_wh_out[NLL*DD*DINN];
__device__ __half g_xph[NLL*XPN*DINN];
__device__ __half g_dtwh[NLL*DINN*DTK];

// ======================= low-level helpers ==================================
__device__ __forceinline__ uint32_t smem_u32(const void* p) {
    uint32_t a;
    asm("{ .reg .u64 t; cvta.to.shared.u64 t, %1; cvt.u32.u64 %0, t; }"
        : "=r"(a) : "l"(p));
    return a;
}
__device__ __forceinline__ void cp_async16(uint32_t dst, const void* src) {
    asm volatile("cp.async.cg.shared.global [%0], [%1], 16;" :: "r"(dst), "l"(src));
}
#define CP_COMMIT() asm volatile("cp.async.commit_group;" ::: "memory")
#define CP_WAIT(N)  asm volatile("cp.async.wait_group %0;" :: "n"(N) : "memory")
#define LDSM_X4(R, addr) \
    asm volatile("ldmatrix.sync.aligned.m8n8.x4.shared.b16 {%0,%1,%2,%3}, [%4];" \
        : "=r"((R)[0]), "=r"((R)[1]), "=r"((R)[2]), "=r"((R)[3]) : "r"(addr))

__device__ __forceinline__ void mma_f16(float* c, const uint32_t* a, const uint32_t* b) {
    asm volatile(
        "mma.sync.aligned.m16n8k16.row.col.f32.f16.f16.f32 "
        "{%0,%1,%2,%3}, {%4,%5,%6,%7}, {%8,%9}, {%0,%1,%2,%3};"
        : "+f"(c[0]), "+f"(c[1]), "+f"(c[2]), "+f"(c[3])
        : "r"(a[0]), "r"(a[1]), "r"(a[2]), "r"(a[3]), "r"(b[0]), "r"(b[1]));
}

// ======================= pure fp16 HGEMM (1 product) =========================
// C[M,N] (+)= A[M,K] * W[N,K]^T ; A,W fp16 (hi planes). 128 x TN CTA tile.
// Split-K via blockIdx.z (klen per split, partStride output offset).
#define BKH    32
#define RP     40     // smem row stride in halves (80B), ldmatrix conflict-free

template<int TN, int WNW, int MAT, int NAT, int STAGES, int THREADS>
__global__ void __launch_bounds__(THREADS)
k_hgemm(const __half* __restrict__ Ah, int lda,
        const __half* __restrict__ Wh, int ldw,
        float* __restrict__ C, int ldc, int klen, long partStride, int accumulate)
{
    extern __shared__ char sm[];
    constexpr int PLA   = 128 * RP * 2;
    constexpr int PLB   = TN  * RP * 2;
    constexpr int STAGE = PLA + PLB;

    const int tid = threadIdx.x, lane = tid & 31, wid = tid >> 5;
    const int wm = wid / WNW, wn = wid % WNW;
    const int m0 = blockIdx.y * 128, n0 = blockIdx.x * TN;
    const int kbase = blockIdx.z * klen;
    C += (long)blockIdx.z * partStride;
    const uint32_t sb = smem_u32(sm);

    const int g  = lane >> 3, lr = lane & 7;
    const int a_row = ((g & 1) ? 8 : 0) + lr;
    const int a_kg  = (g >> 1);
    const int b_row = ((g >> 1) ? 8 : 0) + lr;
    const int b_kg  = (g & 1);

    float acc[MAT][NAT][4];
#pragma unroll
    for (int i = 0; i < MAT; i++)
#pragma unroll
        for (int j = 0; j < NAT; j++)
#pragma unroll
            for (int q = 0; q < 4; q++) acc[i][j][q] = 0.f;

    const int nch = klen / BKH;

    auto load_stage = [&](int st, int ch) {
        const uint32_t sa = sb + st * STAGE;
        const int kb = kbase + ch * BKH;
#pragma unroll
        for (int c = tid; c < 512; c += THREADS) {
            int r = c >> 2, kg = c & 3;
            size_t go = (size_t)(m0 + r) * lda + kb + kg * 8;
            uint32_t so = (uint32_t)(r * (RP*2) + kg * 16);
            cp_async16(sa + so, Ah + go);
        }
#pragma unroll
        for (int c = tid; c < TN*4; c += THREADS) {
            int r = c >> 2, kg = c & 3;
            size_t go = (size_t)(n0 + r) * ldw + kb + kg * 8;
            uint32_t so = (uint32_t)(r * (RP*2) + kg * 16);
            cp_async16(sa + PLA + so, Wh + go);
        }
        CP_COMMIT();
    };

#pragma unroll
    for (int s = 0; s < STAGES - 1; s++) load_stage(s, s);

    for (int ch = 0; ch < nch; ch++) {
        int pre = ch + STAGES - 1;
        if (pre < nch) load_stage(pre % STAGES, pre);
        else           CP_COMMIT();
        CP_WAIT(STAGES - 2);
        __syncthreads();

        const uint32_t sa = sb + (ch % STAGES) * STAGE;
#pragma unroll
        for (int ks = 0; ks < 2; ks++) {
            uint32_t ah[MAT][4], bh[NAT][2];
#pragma unroll
            for (int am = 0; am < MAT; am++) {
                int row = wm * (MAT*16) + am*16 + a_row;
                uint32_t ad = sa + row * (RP*2) + (ks*2 + a_kg) * 16;
                LDSM_X4(ah[am], ad);
            }
#pragma unroll
            for (int p = 0; p < NAT/2; p++) {
                int row = wn * (NAT*8) + p*16 + b_row;
                uint32_t ad = sa + PLA + row * (RP*2) + (ks*2 + b_kg) * 16;
                uint32_t th[4];
                LDSM_X4(th, ad);
                bh[2*p][0]=th[0]; bh[2*p][1]=th[1]; bh[2*p+1][0]=th[2]; bh[2*p+1][1]=th[3];
            }
#pragma unroll
            for (int am = 0; am < MAT; am++)
#pragma unroll
                for (int bn = 0; bn < NAT; bn++)
                    mma_f16(acc[am][bn], ah[am], bh[bn]);
        }
        __syncthreads();
    }

    const int lq = lane & 3, lr4 = lane >> 2;
#pragma unroll
    for (int am = 0; am < MAT; am++) {
        int row = m0 + wm*(MAT*16) + am*16 + lr4;
#pragma unroll
        for (int bn = 0; bn < NAT; bn++) {
            int col = n0 + wn*(NAT*8) + bn*8 + lq*2;
            float* p0 = &C[(size_t)row       * ldc + col];
            float* p1 = &C[(size_t)(row + 8) * ldc + col];
            if (accumulate) {
                float2 o0 = *reinterpret_cast<float2*>(p0);
                float2 o1 = *reinterpret_cast<float2*>(p1);
                o0.x += acc[am][bn][0]; o0.y += acc[am][bn][1];
                o1.x += acc[am][bn][2]; o1.y += acc[am][bn][3];
                *reinterpret_cast<float2*>(p0) = o0;
                *reinterpret_cast<float2*>(p1) = o1;
            } else {
                *reinterpret_cast<float2*>(p0) = make_float2(acc[am][bn][0], acc[am][bn][1]);
                *reinterpret_cast<float2*>(p1) = make_float2(acc[am][bn][2], acc[am][bn][3]);
            }
        }
    }
}

// ---------------- weight conversion kernels ---------------------------------
__global__ void k_split_hi(const float* __restrict__ in, __half* __restrict__ hi, int n4)
{
    int i = blockIdx.x * blockDim.x + threadIdx.x;
    if (i >= n4) return;
    float4 v = reinterpret_cast<const float4*>(in)[i];
    reinterpret_cast<__half2*>(hi)[2*i  ] =
        __halves2half2(__float2half_rn(v.x), __float2half_rn(v.y));
    reinterpret_cast<__half2*>(hi)[2*i+1] =
        __halves2half2(__float2half_rn(v.z), __float2half_rn(v.w));
}

__global__ void k_split_pad_hi(const float* __restrict__ in, __half* __restrict__ hi,
                               int R, int Cc, int PR, int PC, int L)
{
    int idx = blockIdx.x * blockDim.x + threadIdx.x;
    if (idx >= L*PR*PC) return;
    int c = idx % PC, r = (idx / PC) % PR, l = idx / (PC*PR);
    float v = (r < R && c < Cc) ? in[((long)l*R + r)*Cc + c] : 0.f;
    hi[idx] = __float2half_rn(v);
}

// ---------------- x_proj split-K reduce + dt-plane emit ---------------------
__global__ void k_xp_reduce(const float* __restrict__ part,
                            float* __restrict__ dbl, __half* __restrict__ dth)
{
    int idx = blockIdx.x * blockDim.x + threadIdx.x;
    if (idx >= MM*XPN) return;
    int j = idx % XPN, m = idx / XPN;
    float s = 0.f;
#pragma unroll
    for (int p = 0; p < XSPL; p++) s += part[(long)p*MM*XPN + idx];
    if (j < DBLW) dbl[(long)m*DBLW + j] = s;
    if (j < DTK)  dth[(long)m*DTK + j] = __float2half_rn((j < DTRR) ? s : 0.f);
}

// ---------------- permute ----------------------------------------------------
__global__ void k_permute(const float* __restrict__ in, const int* __restrict__ vs,
                          float* __restrict__ out)
{
    int idx = blockIdx.x * blockDim.x + threadIdx.x;
    if (idx >= MM*DD) return;
    int d = idx % DD;
    int m = idx / DD;
    int t = m % VV, b = m / VV;
    int v = vs[b];
    int src = (t + VV - v) % VV;
    out[idx] = in[(b*VV + src)*DD + d];
}

// ---------------- RMSNorm helpers --------------------------------------------
__device__ __forceinline__ float rms_scale(const float* row, int tid, int bdim)
{
    float ss = 0.f;
    for (int i = tid; i < DD; i += bdim) { float v = row[i]; ss += v*v; }
    __shared__ float red[32];
    for (int o = 16; o; o >>= 1) ss += __shfl_xor_sync(0xffffffffu, ss, o);
    if ((tid & 31) == 0) red[tid >> 5] = ss;
    __syncthreads();
    if (tid < 32) {
        float v = (tid < (bdim >> 5)) ? red[tid] : 0.f;
        for (int o = 16; o; o >>= 1) v += __shfl_xor_sync(0xffffffffu, v, o);
        red[tid] = v;
    }
    __syncthreads();
    return rsqrtf(red[0] * (1.f/DD) + 1e-5f);
}

__global__ void k_rmsnorm_h(const float* __restrict__ in, const float* __restrict__ w,
                            __half* __restrict__ oh)
{
    int m = blockIdx.x;
    const float* row = in + m*DD;
    float scale = rms_scale(row, threadIdx.x, blockDim.x);
    for (int i = threadIdx.x; i < DD; i += blockDim.x)
        oh[m*DD + i] = __float2half_rn(row[i] * scale * w[i]);
}

// final RMSNorm fused with reverse circular permute
__global__ void k_rmsnorm_perm(const float* __restrict__ in, const float* __restrict__ w,
                               const int* __restrict__ vs, float* __restrict__ out)
{
    int m = blockIdx.x;
    int t = m % VV, b = m / VV;
    const float* row = in + m*DD;
    float scale = rms_scale(row, threadIdx.x, blockDim.x);
    int v = vs[b];
    int tdst = (t - v + VV) % VV;
    float* orow = out + (long)(b*VV + tdst)*DD;
    for (int i = threadIdx.x; i < DD; i += blockDim.x)
        orow[i] = row[i] * scale * w[i];
}

// ---------------- causal depthwise conv + SiLU -------------------------------
__global__ void k_conv(const float* __restrict__ z, const float* __restrict__ cw,
                       const float* __restrict__ cb, float* __restrict__ uc,
                       __half* __restrict__ uch)
{
    int idx = blockIdx.x * blockDim.x + threadIdx.x;
    if (idx >= MM*DINN) return;
    int d = idx % DINN;
    int m = idx / DINN;
    int t = m % VV, b = m / VV;
    float acc = cb[d];
#pragma unroll
    for (int h = 0; h < DCC; h++) {
        int tt = t + h - (DCC - 1);
        if (tt >= 0) acc += cw[d*DCC + h] * z[(long)(b*VV + tt)*(2*DINN) + d];
    }
    float u = acc / (1.f + __expf(-acc));
    uc[idx] = u;
    uch[idx] = __float2half_rn(u);
}

// ---------------- selective scan (softplus + gate fused; fp16 out) ----------
__global__ void k_scan(const float* __restrict__ delta_raw,
                       const float* __restrict__ dt_b,
                       const float* __restrict__ uc,
                       const float* __restrict__ z,
                       const float* __restrict__ dbl, const float* __restrict__ A_log,
                       const float* __restrict__ Dsk, __half* __restrict__ yh)
{
    __shared__ float sB[VV][DSS];
    __shared__ float sC[VV][DSS];
    const int chunks = DINN / 256;
    int b  = blockIdx.x / chunks;
    int dc = blockIdx.x % chunks;
    int d  = dc * 256 + threadIdx.x;

    for (int i = threadIdx.x; i < VV*DSS; i += 256) {
        int t = i / DSS, s = i % DSS;
        const float* row = dbl + (long)(b*VV + t) * DBLW;
        sB[t][s] = row[DTRR + s];
        sC[t][s] = row[DTRR + DSS + s];
    }
    __syncthreads();

    float a[DSS], h[DSS];
#pragma unroll
    for (int s = 0; s < DSS; s++) {
        a[s] = -expf(A_log[(long)d*DSS + s]);
        h[s] = 0.f;
    }
    float dsk = Dsk[d];
    float bias = dt_b[d];

    for (int t = 0; t < VV; t++) {
        long m = (long)(b*VV + t);
        float dv = delta_raw[m*DINN + d] + bias;
        float dl = fmaxf(dv, 0.f) + log1pf(__expf(-fabsf(dv)));
        float uu = uc[m*DINN + d];
        float du = dl * uu;
        float acc = 0.f;
#pragma unroll
        for (int s = 0; s < DSS; s++) {
            float dA = __expf(dl * a[s]);
            h[s] = dA * h[s] + du * sB[t][s];
            acc += h[s] * sC[t][s];
        }
        float r = z[m*(2*DINN) + DINN + d];
        float yv = (acc + uu * dsk) * (r / (1.f + __expf(-r)));
        yh[m*DINN + d] = __float2half_rn(yv);
    }
}

// ---------------- host orchestration ----------------------------------------
#define PLA_B    (128*RP*2)
#define ST_IN    (PLA_B + 256*RP*2)   // 30720
#define ST_OUT   (PLA_B + 64*RP*2)    // 15360
#define ST_XP    (PLA_B + XPN*RP*2)   // 16640
#define ST_DT    (PLA_B + 128*RP*2)   // 20480
#define SMEM_IN  (4*ST_IN)    // 122880
#define SMEM_OUT (4*ST_OUT)   // 61440
#define SMEM_XP  (3*ST_XP)    // 49920
#define SMEM_DT  (2*ST_DT)    // 40960

extern "C" void kernel_launch(void* const* d_in, const int* in_sizes, int n_in,
                              void* d_out, int out_size)
{
    const float* x        = (const float*)d_in[0];
    const int*   vs       = (const int*)  d_in[1];
    const float* norm_w   = (const float*)d_in[2];
    const float* in_w     = (const float*)d_in[3];
    const float* conv_w   = (const float*)d_in[4];
    const float* conv_b   = (const float*)d_in[5];
    const float* xp_w     = (const float*)d_in[6];
    const float* dt_w     = (const float*)d_in[7];
    const float* dt_b     = (const float*)d_in[8];
    const float* A_log    = (const float*)d_in[9];
    const float* D_skip   = (const float*)d_in[10];
    const float* out_w    = (const float*)d_in[11];
    const float* norm_f_w = (const float*)d_in[12];
    float* out = (float*)d_out;

    cudaFuncSetAttribute((void*)k_hgemm<256,8,4,4,4,512>,
                         cudaFuncAttributeMaxDynamicSharedMemorySize, SMEM_IN);
    cudaFuncSetAttribute((void*)k_hgemm<64,2,2,4,4,256>,
                         cudaFuncAttributeMaxDynamicSharedMemorySize, SMEM_OUT);
    cudaFuncSetAttribute((void*)k_hgemm<XPN,1,1,10,3,256>,
                         cudaFuncAttributeMaxDynamicSharedMemorySize, SMEM_XP);
    cudaFuncSetAttribute((void*)k_hgemm<128,4,4,4,2,256>,
                         cudaFuncAttributeMaxDynamicSharedMemorySize, SMEM_DT);

    float *hb, *z, *uc, *dbl, *delta, *xpp;
    __half *ah, *dth, *whi, *who, *xph, *dtwh;
    cudaGetSymbolAddress((void**)&hb,    g_h);
    cudaGetSymbolAddress((void**)&z,     g_z);
    cudaGetSymbolAddress((void**)&uc,    g_uc);
    cudaGetSymbolAddress((void**)&dbl,   g_dbl);
    cudaGetSymbolAddress((void**)&delta, g_delta);
    cudaGetSymbolAddress((void**)&xpp,   g_xp_part);
    cudaGetSymbolAddress((void**)&ah,    g_ah);
    cudaGetSymbolAddress((void**)&dth,   g_dth);
    cudaGetSymbolAddress((void**)&whi,   g_wh_in);
    cudaGetSymbolAddress((void**)&who,   g_wh_out);
    cudaGetSymbolAddress((void**)&xph,   g_xph);
    cudaGetSymbolAddress((void**)&dtwh,  g_dtwh);

    const int nD   = MM*DD;
    const int nDIN = MM*DINN;

    // weight plane prep (once per launch; deterministic)
    {
        int n4 = NLL*2*DINN*DD/4;
        k_split_hi<<<(n4 + 255)/256, 256>>>(in_w, whi, n4);
        n4 = NLL*DD*DINN/4;
        k_split_hi<<<(n4 + 255)/256, 256>>>(out_w, who, n4);
        int n = NLL*XPN*DINN;
        k_split_pad_hi<<<(n + 255)/256, 256>>>(xp_w, xph, DBLW, DINN, XPN, DINN, NLL);
        n = NLL*DINN*DTK;
        k_split_pad_hi<<<(n + 255)/256, 256>>>(dt_w, dtwh, DINN, DTRR, DINN, DTK, NLL);
    }

    k_permute<<<(nD + 255)/256, 256>>>(x, vs, hb);

    for (int i = 0; i < NLL; i++) {
        k_rmsnorm_h<<<MM, 256>>>(hb, norm_w + (long)i*DD, ah);
        // in_proj (one wave: 150 CTAs of 128x256)
        {
            dim3 grid(2*DINN/256, MM/128);
            k_hgemm<256,8,4,4,4,512><<<grid, 512, SMEM_IN>>>(
                ah, DD, whi + (size_t)i*2*DINN*DD, DD, z, 2*DINN, DD, 0, 0);
        }
        k_conv<<<(nDIN + 255)/256, 256>>>(z, conv_w + (long)i*DINN*DCC,
                                          conv_b + (long)i*DINN, uc, ah);
        // x_proj split-K
        {
            dim3 grid(1, MM/128, XSPL);
            k_hgemm<XPN,1,1,10,3,256><<<grid, 256, SMEM_XP>>>(
                ah, DINN, xph + (size_t)i*XPN*DINN, DINN,
                xpp, XPN, DINN/XSPL, (long)MM*XPN, 0);
            int n = MM*XPN;
            k_xp_reduce<<<(n + 255)/256, 256>>>(xpp, dbl, dth);
        }
        // dt_proj (K padded to 64)
        {
            dim3 grid(DINN/128, MM/128);
            k_hgemm<128,4,4,4,2,256><<<grid, 256, SMEM_DT>>>(
                dth, DTK, dtwh + (size_t)i*DINN*DTK, DTK, delta, DINN, DTK, 0, 0);
        }
        k_scan<<<BB*(DINN/256), 256>>>(delta, dt_b + (long)i*DINN, uc, z, dbl,
                                       A_log + (long)i*DINN*DSS,
                                       D_skip + (long)i*DINN, ah);
        // out_proj accumulate into residual
        {
            dim3 grid(DD/64, MM/128);
            k_hgemm<64,2,2,4,4,256><<<grid, 256, SMEM_OUT>>>(
                ah, DINN, who + (size_t)i*DD*DINN, DINN, hb, DD, DINN, 0, 1);
        }
    }

    k_rmsnorm_perm<<<MM, 256>>>(hb, norm_f_w, vs, out);
}